// round 1
// baseline (speedup 1.0000x reference)
#include <cuda_runtime.h>
#include <cstddef>

// ---------------------------------------------------------------------------
// Problem constants
// ---------------------------------------------------------------------------
#define Mrows   16384          // B*N = 8*2048
#define DMODEL  1024
#define FFDIM   4096
#define NHEADS  16
#define HDIM    32             // head dim D
// LAMBDA_INIT = 0.8 - 0.6*exp(-0.3)
#define LAMBDA_INIT_F        0.35550906759096926f
#define ONE_MINUS_LAMBDA_F   0.64449093240903074f
#define QSCALE               0.17677669529663687f   // 32^-0.5

// ---------------------------------------------------------------------------
// Scratch (device globals -- no allocations allowed)
// ---------------------------------------------------------------------------
__device__ float g_h   [(size_t)Mrows * DMODEL];   // LN1 out
__device__ float g_q   [(size_t)Mrows * DMODEL];
__device__ float g_k   [(size_t)Mrows * DMODEL];
__device__ float g_v   [(size_t)Mrows * DMODEL];
__device__ float g_attn[(size_t)Mrows * DMODEL];   // per-token attn (pre-Wo)
__device__ float g_conn[(size_t)Mrows * DMODEL];   // x + attn@Wo^T + bo
__device__ float g_h2  [(size_t)Mrows * DMODEL];   // LN2 out
__device__ float g_ffn [(size_t)Mrows * FFDIM];    // relu(h2@W1^T+b1)
__device__ float g_lambda;

// ---------------------------------------------------------------------------
// f32x2 packed FMA helpers (Blackwell-only FFMA2 — ptxas never auto-fuses)
// ---------------------------------------------------------------------------
__device__ __forceinline__ unsigned long long pack2(float x, float y) {
    unsigned long long r;
    asm("mov.b64 %0, {%1, %2};" : "=l"(r) : "f"(x), "f"(y));
    return r;
}
__device__ __forceinline__ void unpack2(unsigned long long p, float& x, float& y) {
    asm("mov.b64 {%0, %1}, %2;" : "=f"(x), "=f"(y) : "l"(p));
}
__device__ __forceinline__ void ffma2(unsigned long long& d,
                                      unsigned long long a,
                                      unsigned long long b) {
    asm("fma.rn.f32x2 %0, %1, %2, %0;" : "+l"(d) : "l"(a), "l"(b));
}

// ---------------------------------------------------------------------------
// lambda = exp(dot(lq1,lk1)) - exp(dot(lq2,lk2)) + LAMBDA_INIT
// ---------------------------------------------------------------------------
__global__ void lambda_kernel(const float* __restrict__ lq1,
                              const float* __restrict__ lq2,
                              const float* __restrict__ lk1,
                              const float* __restrict__ lk2) {
    int l = threadIdx.x;                      // 32 threads
    float s1 = lq1[l] * lk1[l];
    float s2 = lq2[l] * lk2[l];
    #pragma unroll
    for (int o = 16; o; o >>= 1) {
        s1 += __shfl_xor_sync(0xffffffffu, s1, o);
        s2 += __shfl_xor_sync(0xffffffffu, s2, o);
    }
    if (l == 0) g_lambda = expf(s1) - expf(s2) + LAMBDA_INIT_F;
}

// ---------------------------------------------------------------------------
// LayerNorm: one block (256 thr) per row of 1024
// ---------------------------------------------------------------------------
__global__ __launch_bounds__(256) void ln_kernel(const float* __restrict__ X,
                                                 const float* __restrict__ G,
                                                 const float* __restrict__ Bb,
                                                 float* __restrict__ Y) {
    size_t row = blockIdx.x;
    int t = threadIdx.x;
    const float4 v = ((const float4*)(X + row * DMODEL))[t];
    float s  = v.x + v.y + v.z + v.w;
    float ss = v.x * v.x + v.y * v.y + v.z * v.z + v.w * v.w;
    #pragma unroll
    for (int o = 16; o; o >>= 1) {
        s  += __shfl_xor_sync(0xffffffffu, s,  o);
        ss += __shfl_xor_sync(0xffffffffu, ss, o);
    }
    __shared__ float sh_s[8], sh_ss[8];
    int w = t >> 5, l = t & 31;
    if (l == 0) { sh_s[w] = s; sh_ss[w] = ss; }
    __syncthreads();
    if (w == 0) {
        float a  = (l < 8) ? sh_s[l]  : 0.0f;
        float bq = (l < 8) ? sh_ss[l] : 0.0f;
        #pragma unroll
        for (int o = 4; o; o >>= 1) {
            a  += __shfl_xor_sync(0xffffffffu, a,  o);
            bq += __shfl_xor_sync(0xffffffffu, bq, o);
        }
        if (l == 0) { sh_s[0] = a; sh_ss[0] = bq; }
    }
    __syncthreads();
    float S = sh_s[0], SS = sh_ss[0];
    float mu  = S * (1.0f / DMODEL);
    float var = SS * (1.0f / DMODEL) - mu * mu;
    float inv = rsqrtf(var + 1e-5f);
    const float4 gg = ((const float4*)G)[t];
    const float4 bb = ((const float4*)Bb)[t];
    float4 o;
    o.x = (v.x - mu) * inv * gg.x + bb.x;
    o.y = (v.y - mu) * inv * gg.y + bb.y;
    o.z = (v.z - mu) * inv * gg.z + bb.z;
    o.w = (v.w - mu) * inv * gg.w + bb.w;
    ((float4*)(Y + row * DMODEL))[t] = o;
}

// ---------------------------------------------------------------------------
// SGEMM: C[M,N] = A[M,K] @ W[N,K]^T  (+bias, +relu, +residual per EPI flags)
// 128x128 tile, BK=16, 256 threads, 8x8 microtile, f32x2 packed FMA
// EPI bit0: +bias[n]   bit1: relu   bit2: +res[m*N+n]
// ---------------------------------------------------------------------------
template <int EPI>
__global__ __launch_bounds__(256) void sgemm(const float* __restrict__ A,
                                             const float* __restrict__ W,
                                             const float* __restrict__ bias,
                                             const float* __restrict__ res,
                                             float* __restrict__ C,
                                             int Nn, int K) {
    __shared__ __align__(16) float As[16][128];
    __shared__ __align__(16) float Bs[16][128];

    const int tid = threadIdx.x;
    const int tx = tid & 15;        // 0..15 -> n
    const int ty = tid >> 4;        // 0..15 -> m
    const int m0 = blockIdx.y * 128;
    const int n0 = blockIdx.x * 128;

    unsigned long long acc[8][4];
    #pragma unroll
    for (int i = 0; i < 8; i++)
        #pragma unroll
        for (int j = 0; j < 4; j++) acc[i][j] = 0ULL;

    for (int k0 = 0; k0 < K; k0 += 16) {
        #pragma unroll
        for (int i = 0; i < 2; i++) {
            int f = tid + i * 256;          // 0..511
            int row = f >> 2;               // 0..127
            int c4  = (f & 3) * 4;          // 0,4,8,12
            float4 va = *(const float4*)(A + (size_t)(m0 + row) * K + k0 + c4);
            As[c4 + 0][row] = va.x; As[c4 + 1][row] = va.y;
            As[c4 + 2][row] = va.z; As[c4 + 3][row] = va.w;
            float4 vb = *(const float4*)(W + (size_t)(n0 + row) * K + k0 + c4);
            Bs[c4 + 0][row] = vb.x; Bs[c4 + 1][row] = vb.y;
            Bs[c4 + 2][row] = vb.z; Bs[c4 + 3][row] = vb.w;
        }
        __syncthreads();
        #pragma unroll
        for (int kk = 0; kk < 16; kk++) {
            float4 a0 = *(const float4*)&As[kk][ty * 8];
            float4 a1 = *(const float4*)&As[kk][ty * 8 + 4];
            ulonglong2 b0 = *(const ulonglong2*)&Bs[kk][tx * 8];
            ulonglong2 b1 = *(const ulonglong2*)&Bs[kk][tx * 8 + 4];
            unsigned long long bp0 = b0.x, bp1 = b0.y, bp2 = b1.x, bp3 = b1.y;
            float av[8] = {a0.x, a0.y, a0.z, a0.w, a1.x, a1.y, a1.z, a1.w};
            #pragma unroll
            for (int i = 0; i < 8; i++) {
                unsigned long long ap = pack2(av[i], av[i]);
                ffma2(acc[i][0], ap, bp0);
                ffma2(acc[i][1], ap, bp1);
                ffma2(acc[i][2], ap, bp2);
                ffma2(acc[i][3], ap, bp3);
            }
        }
        __syncthreads();
    }

    // epilogue
    float bvals[8];
    if (EPI & 1) {
        float4 b0 = *(const float4*)(bias + n0 + tx * 8);
        float4 b1 = *(const float4*)(bias + n0 + tx * 8 + 4);
        bvals[0] = b0.x; bvals[1] = b0.y; bvals[2] = b0.z; bvals[3] = b0.w;
        bvals[4] = b1.x; bvals[5] = b1.y; bvals[6] = b1.z; bvals[7] = b1.w;
    }
    #pragma unroll
    for (int i = 0; i < 8; i++) {
        int m = m0 + ty * 8 + i;
        size_t base = (size_t)m * Nn + n0 + tx * 8;
        float o[8];
        #pragma unroll
        for (int j2 = 0; j2 < 4; j2++) unpack2(acc[i][j2], o[2 * j2], o[2 * j2 + 1]);
        if (EPI & 1) {
            #pragma unroll
            for (int j = 0; j < 8; j++) o[j] += bvals[j];
        }
        if (EPI & 2) {
            #pragma unroll
            for (int j = 0; j < 8; j++) o[j] = fmaxf(o[j], 0.0f);
        }
        if (EPI & 4) {
            float4 r0 = *(const float4*)(res + base);
            float4 r1 = *(const float4*)(res + base + 4);
            o[0] += r0.x; o[1] += r0.y; o[2] += r0.z; o[3] += r0.w;
            o[4] += r1.x; o[5] += r1.y; o[6] += r1.z; o[7] += r1.w;
        }
        float4 s0 = {o[0], o[1], o[2], o[3]};
        float4 s1 = {o[4], o[5], o[6], o[7]};
        *(float4*)(C + base)     = s0;
        *(float4*)(C + base + 4) = s1;
    }
}

// ---------------------------------------------------------------------------
// Per-token differential attention. One warp per token, 2 warps per block.
// q,k rearranged 'h d j' -> row (j*16+h), col d.  att 32x32, softmax over 32,
// w[a][h] = p[a][h] - lam*p[16+a][16+h]; out[a][:] = sum_h w*v[h][:];
// rmsnorm(64) * (1-LAMBDA_INIT).
// ---------------------------------------------------------------------------
__global__ __launch_bounds__(64) void attn_kernel(const float* __restrict__ Q,
                                                  const float* __restrict__ K,
                                                  const float* __restrict__ V,
                                                  float* __restrict__ O) {
    __shared__ float s_q[2][32][33];   // later reused as softmax probs
    __shared__ float s_k[2][32][32];
    __shared__ float s_v[2][16][64];

    const int warp = threadIdx.x >> 5;
    const int lane = threadIdx.x & 31;
    const size_t t = (size_t)blockIdx.x * 2 + warp;

    const float* q = Q + t * DMODEL;
    const float* k = K + t * DMODEL;
    const float* v = V + t * DMODEL;
    float (*qs)[33] = s_q[warp];
    float (*ks)[32] = s_k[warp];
    float (*vs)[64] = s_v[warp];

    for (int idx = lane; idx < DMODEL; idx += 32) {
        int h = idx >> 6, r = idx & 63;
        int dd = r >> 1, j = r & 1;
        qs[j * 16 + h][dd] = q[idx] * QSCALE;
        ks[j * 16 + h][dd] = k[idx];
        ((float*)vs)[idx]  = v[idx];
    }
    __syncwarp();

    // my q row
    float qr[32];
    #pragma unroll
    for (int d = 0; d < 32; d++) qr[d] = qs[lane][d];

    // scores row 'lane' vs all 32 k rows
    float p[32];
    #pragma unroll
    for (int j = 0; j < 32; j++) {
        float s = 0.0f;
        #pragma unroll
        for (int d = 0; d < 32; d++) s += qr[d] * ks[j][d];
        p[j] = s;
    }
    // softmax over 32
    float mx = p[0];
    #pragma unroll
    for (int j = 1; j < 32; j++) mx = fmaxf(mx, p[j]);
    float sum = 0.0f;
    #pragma unroll
    for (int j = 0; j < 32; j++) { p[j] = expf(p[j] - mx); sum += p[j]; }
    float rinv = 1.0f / sum;
    __syncwarp();
    #pragma unroll
    for (int j = 0; j < 32; j++) qs[lane][j] = p[j] * rinv;   // reuse qs as probs
    __syncwarp();

    const float lam = g_lambda;
    const int a = lane & 15;
    const int half = lane >> 4;          // which 32-col half of the 64-dim v
    float accv[32];
    #pragma unroll
    for (int e = 0; e < 32; e++) accv[e] = 0.0f;
    #pragma unroll
    for (int h = 0; h < 16; h++) {
        float w = qs[a][h] - lam * qs[16 + a][16 + h];
        const float* vrow = &vs[h][half * 32];
        #pragma unroll
        for (int e = 0; e < 32; e++) accv[e] += w * vrow[e];
    }
    // rmsnorm over the 64 outputs of row a (split across lane pair a / a+16)
    float ss = 0.0f;
    #pragma unroll
    for (int e = 0; e < 32; e++) ss += accv[e] * accv[e];
    ss += __shfl_xor_sync(0xffffffffu, ss, 16);
    float scale = rsqrtf(ss * (1.0f / 64.0f) + 1e-5f) * ONE_MINUS_LAMBDA_F;

    float* o = O + t * DMODEL + a * 64 + half * 32;
    #pragma unroll
    for (int e4 = 0; e4 < 8; e4++) {
        float4 w4 = {accv[e4 * 4] * scale, accv[e4 * 4 + 1] * scale,
                     accv[e4 * 4 + 2] * scale, accv[e4 * 4 + 3] * scale};
        *(float4*)(o + e4 * 4) = w4;
    }
}

// ---------------------------------------------------------------------------
// launch
// ---------------------------------------------------------------------------
extern "C" void kernel_launch(void* const* d_in, const int* in_sizes, int n_in,
                              void* d_out, int out_size) {
    const float* x    = (const float*)d_in[0];
    const float* Wq   = (const float*)d_in[1];
    const float* Wk   = (const float*)d_in[2];
    const float* Wv   = (const float*)d_in[3];
    const float* lq1  = (const float*)d_in[4];
    const float* lq2  = (const float*)d_in[5];
    const float* lk1  = (const float*)d_in[6];
    const float* lk2  = (const float*)d_in[7];
    const float* Wo   = (const float*)d_in[8];
    const float* bo   = (const float*)d_in[9];
    const float* ln1g = (const float*)d_in[10];
    const float* ln1b = (const float*)d_in[11];
    const float* ln2g = (const float*)d_in[12];
    const float* ln2b = (const float*)d_in[13];
    const float* W1   = (const float*)d_in[14];
    const float* b1   = (const float*)d_in[15];
    const float* W2   = (const float*)d_in[16];
    const float* b2   = (const float*)d_in[17];
    float* out = (float*)d_out;

    float *ph, *pq, *pk, *pv, *pattn, *pconn, *ph2, *pffn;
    cudaGetSymbolAddress((void**)&ph,    g_h);
    cudaGetSymbolAddress((void**)&pq,    g_q);
    cudaGetSymbolAddress((void**)&pk,    g_k);
    cudaGetSymbolAddress((void**)&pv,    g_v);
    cudaGetSymbolAddress((void**)&pattn, g_attn);
    cudaGetSymbolAddress((void**)&pconn, g_conn);
    cudaGetSymbolAddress((void**)&ph2,   g_h2);
    cudaGetSymbolAddress((void**)&pffn,  g_ffn);

    lambda_kernel<<<1, 32>>>(lq1, lq2, lk1, lk2);

    // LN1: x -> h
    ln_kernel<<<Mrows, 256>>>(x, ln1g, ln1b, ph);

    dim3 gq(DMODEL / 128, Mrows / 128);   // (8,128)
    sgemm<0><<<gq, 256>>>(ph, Wq, nullptr, nullptr, pq, DMODEL, DMODEL);
    sgemm<0><<<gq, 256>>>(ph, Wk, nullptr, nullptr, pk, DMODEL, DMODEL);
    sgemm<0><<<gq, 256>>>(ph, Wv, nullptr, nullptr, pv, DMODEL, DMODEL);

    attn_kernel<<<Mrows / 2, 64>>>(pq, pk, pv, pattn);

    // conn = x + attn @ Wo^T + bo
    sgemm<5><<<gq, 256>>>(pattn, Wo, bo, x, pconn, DMODEL, DMODEL);

    // LN2: conn -> h2
    ln_kernel<<<Mrows, 256>>>(pconn, ln2g, ln2b, ph2);

    // ffn = relu(h2 @ W1^T + b1)
    dim3 g1(FFDIM / 128, Mrows / 128);    // (32,128)
    sgemm<3><<<g1, 256>>>(ph2, W1, b1, nullptr, pffn, FFDIM, DMODEL);

    // out = conn + ffn @ W2^T + b2
    sgemm<5><<<gq, 256>>>(pffn, W2, b2, pconn, out, DMODEL, FFDIM);
}

// round 2
// speedup vs baseline: 1.0003x; 1.0003x over previous
#include <cuda_runtime.h>
#include <cstddef>

// ---------------------------------------------------------------------------
// Problem constants
// ---------------------------------------------------------------------------
#define Mrows   16384          // B*N = 8*2048
#define DMODEL  1024
#define FFDIM   4096
#define NHEADS  16
#define HDIM    32             // head dim D
// LAMBDA_INIT = 0.8 - 0.6*exp(-0.3)
#define LAMBDA_INIT_F        0.35550906759096926f
#define ONE_MINUS_LAMBDA_F   0.64449093240903074f
#define QSCALE               0.17677669529663687f   // 32^-0.5

// ---------------------------------------------------------------------------
// Scratch (device globals -- no allocations allowed)
// ---------------------------------------------------------------------------
__device__ float g_h   [(size_t)Mrows * DMODEL];   // LN1 out
__device__ float g_q   [(size_t)Mrows * DMODEL];
__device__ float g_k   [(size_t)Mrows * DMODEL];
__device__ float g_v   [(size_t)Mrows * DMODEL];
__device__ float g_attn[(size_t)Mrows * DMODEL];   // per-token attn (pre-Wo)
__device__ float g_conn[(size_t)Mrows * DMODEL];   // x + attn@Wo^T + bo
__device__ float g_h2  [(size_t)Mrows * DMODEL];   // LN2 out
__device__ float g_ffn [(size_t)Mrows * FFDIM];    // relu(h2@W1^T+b1)
__device__ float g_lambda;

// ---------------------------------------------------------------------------
// f32x2 packed FMA helpers (Blackwell-only FFMA2 — ptxas never auto-fuses)
// ---------------------------------------------------------------------------
__device__ __forceinline__ unsigned long long pack2(float x, float y) {
    unsigned long long r;
    asm("mov.b64 %0, {%1, %2};" : "=l"(r) : "f"(x), "f"(y));
    return r;
}
__device__ __forceinline__ void unpack2(unsigned long long p, float& x, float& y) {
    asm("mov.b64 {%0, %1}, %2;" : "=f"(x), "=f"(y) : "l"(p));
}
__device__ __forceinline__ void ffma2(unsigned long long& d,
                                      unsigned long long a,
                                      unsigned long long b) {
    asm("fma.rn.f32x2 %0, %1, %2, %0;" : "+l"(d) : "l"(a), "l"(b));
}

// ---------------------------------------------------------------------------
// lambda = exp(dot(lq1,lk1)) - exp(dot(lq2,lk2)) + LAMBDA_INIT
// ---------------------------------------------------------------------------
__global__ void lambda_kernel(const float* __restrict__ lq1,
                              const float* __restrict__ lq2,
                              const float* __restrict__ lk1,
                              const float* __restrict__ lk2) {
    int l = threadIdx.x;                      // 32 threads
    float s1 = lq1[l] * lk1[l];
    float s2 = lq2[l] * lk2[l];
    #pragma unroll
    for (int o = 16; o; o >>= 1) {
        s1 += __shfl_xor_sync(0xffffffffu, s1, o);
        s2 += __shfl_xor_sync(0xffffffffu, s2, o);
    }
    if (l == 0) g_lambda = expf(s1) - expf(s2) + LAMBDA_INIT_F;
}

// ---------------------------------------------------------------------------
// LayerNorm: one block (256 thr) per row of 1024
// ---------------------------------------------------------------------------
__global__ __launch_bounds__(256) void ln_kernel(const float* __restrict__ X,
                                                 const float* __restrict__ G,
                                                 const float* __restrict__ Bb,
                                                 float* __restrict__ Y) {
    size_t row = blockIdx.x;
    int t = threadIdx.x;
    const float4 v = ((const float4*)(X + row * DMODEL))[t];
    float s  = v.x + v.y + v.z + v.w;
    float ss = v.x * v.x + v.y * v.y + v.z * v.z + v.w * v.w;
    #pragma unroll
    for (int o = 16; o; o >>= 1) {
        s  += __shfl_xor_sync(0xffffffffu, s,  o);
        ss += __shfl_xor_sync(0xffffffffu, ss, o);
    }
    __shared__ float sh_s[8], sh_ss[8];
    int w = t >> 5, l = t & 31;
    if (l == 0) { sh_s[w] = s; sh_ss[w] = ss; }
    __syncthreads();
    if (w == 0) {
        float a  = (l < 8) ? sh_s[l]  : 0.0f;
        float bq = (l < 8) ? sh_ss[l] : 0.0f;
        #pragma unroll
        for (int o = 4; o; o >>= 1) {
            a  += __shfl_xor_sync(0xffffffffu, a,  o);
            bq += __shfl_xor_sync(0xffffffffu, bq, o);
        }
        if (l == 0) { sh_s[0] = a; sh_ss[0] = bq; }
    }
    __syncthreads();
    float S = sh_s[0], SS = sh_ss[0];
    float mu  = S * (1.0f / DMODEL);
    float var = SS * (1.0f / DMODEL) - mu * mu;
    float inv = rsqrtf(var + 1e-5f);
    const float4 gg = ((const float4*)G)[t];
    const float4 bb = ((const float4*)Bb)[t];
    float4 o;
    o.x = (v.x - mu) * inv * gg.x + bb.x;
    o.y = (v.y - mu) * inv * gg.y + bb.y;
    o.z = (v.z - mu) * inv * gg.z + bb.z;
    o.w = (v.w - mu) * inv * gg.w + bb.w;
    ((float4*)(Y + row * DMODEL))[t] = o;
}

// ---------------------------------------------------------------------------
// SGEMM: C[M,N] = A[M,K] @ W[N,K]^T  (+bias, +relu, +residual per EPI flags)
// 128x128 tile, BK=16, 256 threads, 8x8 microtile, f32x2 packed FMA
// EPI bit0: +bias[n]   bit1: relu   bit2: +res[m*N+n]
// ---------------------------------------------------------------------------
template <int EPI>
__global__ __launch_bounds__(256) void sgemm(const float* __restrict__ A,
                                             const float* __restrict__ W,
                                             const float* __restrict__ bias,
                                             const float* __restrict__ res,
                                             float* __restrict__ C,
                                             int Nn, int K) {
    __shared__ __align__(16) float As[16][128];
    __shared__ __align__(16) float Bs[16][128];

    const int tid = threadIdx.x;
    const int tx = tid & 15;        // 0..15 -> n
    const int ty = tid >> 4;        // 0..15 -> m
    const int m0 = blockIdx.y * 128;
    const int n0 = blockIdx.x * 128;

    unsigned long long acc[8][4];
    #pragma unroll
    for (int i = 0; i < 8; i++)
        #pragma unroll
        for (int j = 0; j < 4; j++) acc[i][j] = 0ULL;

    for (int k0 = 0; k0 < K; k0 += 16) {
        #pragma unroll
        for (int i = 0; i < 2; i++) {
            int f = tid + i * 256;          // 0..511
            int row = f >> 2;               // 0..127
            int c4  = (f & 3) * 4;          // 0,4,8,12
            float4 va = *(const float4*)(A + (size_t)(m0 + row) * K + k0 + c4);
            As[c4 + 0][row] = va.x; As[c4 + 1][row] = va.y;
            As[c4 + 2][row] = va.z; As[c4 + 3][row] = va.w;
            float4 vb = *(const float4*)(W + (size_t)(n0 + row) * K + k0 + c4);
            Bs[c4 + 0][row] = vb.x; Bs[c4 + 1][row] = vb.y;
            Bs[c4 + 2][row] = vb.z; Bs[c4 + 3][row] = vb.w;
        }
        __syncthreads();
        #pragma unroll
        for (int kk = 0; kk < 16; kk++) {
            float4 a0 = *(const float4*)&As[kk][ty * 8];
            float4 a1 = *(const float4*)&As[kk][ty * 8 + 4];
            ulonglong2 b0 = *(const ulonglong2*)&Bs[kk][tx * 8];
            ulonglong2 b1 = *(const ulonglong2*)&Bs[kk][tx * 8 + 4];
            unsigned long long bp0 = b0.x, bp1 = b0.y, bp2 = b1.x, bp3 = b1.y;
            float av[8] = {a0.x, a0.y, a0.z, a0.w, a1.x, a1.y, a1.z, a1.w};
            #pragma unroll
            for (int i = 0; i < 8; i++) {
                unsigned long long ap = pack2(av[i], av[i]);
                ffma2(acc[i][0], ap, bp0);
                ffma2(acc[i][1], ap, bp1);
                ffma2(acc[i][2], ap, bp2);
                ffma2(acc[i][3], ap, bp3);
            }
        }
        __syncthreads();
    }

    // epilogue
    float bvals[8];
    if (EPI & 1) {
        float4 b0 = *(const float4*)(bias + n0 + tx * 8);
        float4 b1 = *(const float4*)(bias + n0 + tx * 8 + 4);
        bvals[0] = b0.x; bvals[1] = b0.y; bvals[2] = b0.z; bvals[3] = b0.w;
        bvals[4] = b1.x; bvals[5] = b1.y; bvals[6] = b1.z; bvals[7] = b1.w;
    }
    #pragma unroll
    for (int i = 0; i < 8; i++) {
        int m = m0 + ty * 8 + i;
        size_t base = (size_t)m * Nn + n0 + tx * 8;
        float o[8];
        #pragma unroll
        for (int j2 = 0; j2 < 4; j2++) unpack2(acc[i][j2], o[2 * j2], o[2 * j2 + 1]);
        if (EPI & 1) {
            #pragma unroll
            for (int j = 0; j < 8; j++) o[j] += bvals[j];
        }
        if (EPI & 2) {
            #pragma unroll
            for (int j = 0; j < 8; j++) o[j] = fmaxf(o[j], 0.0f);
        }
        if (EPI & 4) {
            float4 r0 = *(const float4*)(res + base);
            float4 r1 = *(const float4*)(res + base + 4);
            o[0] += r0.x; o[1] += r0.y; o[2] += r0.z; o[3] += r0.w;
            o[4] += r1.x; o[5] += r1.y; o[6] += r1.z; o[7] += r1.w;
        }
        float4 s0 = {o[0], o[1], o[2], o[3]};
        float4 s1 = {o[4], o[5], o[6], o[7]};
        *(float4*)(C + base)     = s0;
        *(float4*)(C + base + 4) = s1;
    }
}

// ---------------------------------------------------------------------------
// Per-token differential attention. One warp per token, 2 warps per block.
// q,k rearranged 'h d j' -> row (j*16+h), col d.  att 32x32, softmax over 32,
// w[a][h] = p[a][h] - lam*p[16+a][16+h]; out[a][:] = sum_h w*v[h][:];
// rmsnorm(64) * (1-LAMBDA_INIT).
// ---------------------------------------------------------------------------
__global__ __launch_bounds__(64) void attn_kernel(const float* __restrict__ Q,
                                                  const float* __restrict__ K,
                                                  const float* __restrict__ V,
                                                  float* __restrict__ O) {
    __shared__ float s_q[2][32][33];   // later reused as softmax probs
    __shared__ float s_k[2][32][32];
    __shared__ float s_v[2][16][64];

    const int warp = threadIdx.x >> 5;
    const int lane = threadIdx.x & 31;
    const size_t t = (size_t)blockIdx.x * 2 + warp;

    const float* q = Q + t * DMODEL;
    const float* k = K + t * DMODEL;
    const float* v = V + t * DMODEL;
    float (*qs)[33] = s_q[warp];
    float (*ks)[32] = s_k[warp];
    float (*vs)[64] = s_v[warp];

    for (int idx = lane; idx < DMODEL; idx += 32) {
        int h = idx >> 6, r = idx & 63;
        int dd = r >> 1, j = r & 1;
        qs[j * 16 + h][dd] = q[idx] * QSCALE;
        ks[j * 16 + h][dd] = k[idx];
        ((float*)vs)[idx]  = v[idx];
    }
    __syncwarp();

    // my q row
    float qr[32];
    #pragma unroll
    for (int d = 0; d < 32; d++) qr[d] = qs[lane][d];

    // scores row 'lane' vs all 32 k rows
    float p[32];
    #pragma unroll
    for (int j = 0; j < 32; j++) {
        float s = 0.0f;
        #pragma unroll
        for (int d = 0; d < 32; d++) s += qr[d] * ks[j][d];
        p[j] = s;
    }
    // softmax over 32
    float mx = p[0];
    #pragma unroll
    for (int j = 1; j < 32; j++) mx = fmaxf(mx, p[j]);
    float sum = 0.0f;
    #pragma unroll
    for (int j = 0; j < 32; j++) { p[j] = expf(p[j] - mx); sum += p[j]; }
    float rinv = 1.0f / sum;
    __syncwarp();
    #pragma unroll
    for (int j = 0; j < 32; j++) qs[lane][j] = p[j] * rinv;   // reuse qs as probs
    __syncwarp();

    const float lam = g_lambda;
    const int a = lane & 15;
    const int half = lane >> 4;          // which 32-col half of the 64-dim v
    float accv[32];
    #pragma unroll
    for (int e = 0; e < 32; e++) accv[e] = 0.0f;
    #pragma unroll
    for (int h = 0; h < 16; h++) {
        float w = qs[a][h] - lam * qs[16 + a][16 + h];
        const float* vrow = &vs[h][half * 32];
        #pragma unroll
        for (int e = 0; e < 32; e++) accv[e] += w * vrow[e];
    }
    // rmsnorm over the 64 outputs of row a (split across lane pair a / a+16)
    float ss = 0.0f;
    #pragma unroll
    for (int e = 0; e < 32; e++) ss += accv[e] * accv[e];
    ss += __shfl_xor_sync(0xffffffffu, ss, 16);
    float scale = rsqrtf(ss * (1.0f / 64.0f) + 1e-5f) * ONE_MINUS_LAMBDA_F;

    float* o = O + t * DMODEL + a * 64 + half * 32;
    #pragma unroll
    for (int e4 = 0; e4 < 8; e4++) {
        float4 w4 = {accv[e4 * 4] * scale, accv[e4 * 4 + 1] * scale,
                     accv[e4 * 4 + 2] * scale, accv[e4 * 4 + 3] * scale};
        *(float4*)(o + e4 * 4) = w4;
    }
}

// ---------------------------------------------------------------------------
// launch
// ---------------------------------------------------------------------------
extern "C" void kernel_launch(void* const* d_in, const int* in_sizes, int n_in,
                              void* d_out, int out_size) {
    const float* x    = (const float*)d_in[0];
    const float* Wq   = (const float*)d_in[1];
    const float* Wk   = (const float*)d_in[2];
    const float* Wv   = (const float*)d_in[3];
    const float* lq1  = (const float*)d_in[4];
    const float* lq2  = (const float*)d_in[5];
    const float* lk1  = (const float*)d_in[6];
    const float* lk2  = (const float*)d_in[7];
    const float* Wo   = (const float*)d_in[8];
    const float* bo   = (const float*)d_in[9];
    const float* ln1g = (const float*)d_in[10];
    const float* ln1b = (const float*)d_in[11];
    const float* ln2g = (const float*)d_in[12];
    const float* ln2b = (const float*)d_in[13];
    const float* W1   = (const float*)d_in[14];
    const float* b1   = (const float*)d_in[15];
    const float* W2   = (const float*)d_in[16];
    const float* b2   = (const float*)d_in[17];
    float* out = (float*)d_out;

    float *ph, *pq, *pk, *pv, *pattn, *pconn, *ph2, *pffn;
    cudaGetSymbolAddress((void**)&ph,    g_h);
    cudaGetSymbolAddress((void**)&pq,    g_q);
    cudaGetSymbolAddress((void**)&pk,    g_k);
    cudaGetSymbolAddress((void**)&pv,    g_v);
    cudaGetSymbolAddress((void**)&pattn, g_attn);
    cudaGetSymbolAddress((void**)&pconn, g_conn);
    cudaGetSymbolAddress((void**)&ph2,   g_h2);
    cudaGetSymbolAddress((void**)&pffn,  g_ffn);

    lambda_kernel<<<1, 32>>>(lq1, lq2, lk1, lk2);

    // LN1: x -> h
    ln_kernel<<<Mrows, 256>>>(x, ln1g, ln1b, ph);

    dim3 gq(DMODEL / 128, Mrows / 128);   // (8,128)
    sgemm<0><<<gq, 256>>>(ph, Wq, nullptr, nullptr, pq, DMODEL, DMODEL);
    sgemm<0><<<gq, 256>>>(ph, Wk, nullptr, nullptr, pk, DMODEL, DMODEL);
    sgemm<0><<<gq, 256>>>(ph, Wv, nullptr, nullptr, pv, DMODEL, DMODEL);

    attn_kernel<<<Mrows / 2, 64>>>(pq, pk, pv, pattn);

    // conn = x + attn @ Wo^T + bo
    sgemm<5><<<gq, 256>>>(pattn, Wo, bo, x, pconn, DMODEL, DMODEL);

    // LN2: conn -> h2
    ln_kernel<<<Mrows, 256>>>(pconn, ln2g, ln2b, ph2);

    // ffn = relu(h2 @ W1^T + b1)
    dim3 g1(FFDIM / 128, Mrows / 128);    // (32,128)
    sgemm<3><<<g1, 256>>>(ph2, W1, b1, nullptr, pffn, FFDIM, DMODEL);

    // out = conn + ffn @ W2^T + b2
    sgemm<5><<<gq, 256>>>(pffn, W2, b2, pconn, out, DMODEL, FFDIM);
}

// round 4
// speedup vs baseline: 2.1371x; 2.1364x over previous
#include <cuda_runtime.h>
#include <cuda_bf16.h>
#include <cstdint>
#include <cstddef>

#define Mrows   16384
#define DMODEL  1024
#define FFDIM   4096
#define LAMBDA_INIT_F        0.35550906759096926f
#define ONE_MINUS_LAMBDA_F   0.64449093240903074f
#define QSCALE               0.17677669529663687f

// ---------------- scratch (device globals; no runtime allocs) ----------------
// Activations: [M, 3K] layout = [hi | lo | hi]
// Weights:     [N, 3K] layout = [hi | hi | lo]
__device__ __align__(256) __nv_bfloat16 g_hbf   [(size_t)Mrows * 3 * DMODEL];
__device__ __align__(256) float         g_q     [(size_t)Mrows * DMODEL];
__device__ __align__(256) float         g_k     [(size_t)Mrows * DMODEL];
__device__ __align__(256) float         g_v     [(size_t)Mrows * DMODEL];
__device__ __align__(256) __nv_bfloat16 g_attnbf[(size_t)Mrows * 3 * DMODEL];
__device__ __align__(256) float         g_conn  [(size_t)Mrows * DMODEL];
__device__ __align__(256) __nv_bfloat16 g_h2bf  [(size_t)Mrows * 3 * DMODEL];
__device__ __align__(256) __nv_bfloat16 g_ffnbf [(size_t)Mrows * 3 * FFDIM];
__device__ __align__(256) __nv_bfloat16 g_wq    [(size_t)DMODEL * 3 * DMODEL];
__device__ __align__(256) __nv_bfloat16 g_wk    [(size_t)DMODEL * 3 * DMODEL];
__device__ __align__(256) __nv_bfloat16 g_wv    [(size_t)DMODEL * 3 * DMODEL];
__device__ __align__(256) __nv_bfloat16 g_wo    [(size_t)DMODEL * 3 * DMODEL];
__device__ __align__(256) __nv_bfloat16 g_w1    [(size_t)FFDIM  * 3 * DMODEL];
__device__ __align__(256) __nv_bfloat16 g_w2    [(size_t)DMODEL * 3 * FFDIM];
__device__ float g_lambda;

// ---------------- PTX helpers (base sm_103 target only; no 'a' features) -----
__device__ __forceinline__ uint32_t smem_u32(const void* p) {
    uint32_t a;
    asm("{ .reg .u64 t; cvta.to.shared.u64 t, %1; cvt.u32.u64 %0, t; }" : "=r"(a) : "l"(p));
    return a;
}
__device__ __forceinline__ void cpasync16(uint32_t d, const void* g) {
    asm volatile("cp.async.cg.shared.global [%0], [%1], 16;" :: "r"(d), "l"(g));
}
#define CP_COMMIT()  asm volatile("cp.async.commit_group;" ::: "memory")
#define CP_WAIT1()   asm volatile("cp.async.wait_group 1;" ::: "memory")
#define CP_WAIT0()   asm volatile("cp.async.wait_group 0;" ::: "memory")

#define LDMX4(r, addr) \
    asm volatile("ldmatrix.sync.aligned.m8n8.x4.shared.b16 {%0,%1,%2,%3}, [%4];" \
                 : "=r"((r)[0]), "=r"((r)[1]), "=r"((r)[2]), "=r"((r)[3]) : "r"(addr))

__device__ __forceinline__ void mma16816(float& c0, float& c1, float& c2, float& c3,
                                         uint32_t a0, uint32_t a1, uint32_t a2, uint32_t a3,
                                         uint32_t b0, uint32_t b1) {
    asm volatile(
        "mma.sync.aligned.m16n8k16.row.col.f32.bf16.bf16.f32 "
        "{%0,%1,%2,%3}, {%4,%5,%6,%7}, {%8,%9}, {%0,%1,%2,%3};"
        : "+f"(c0), "+f"(c1), "+f"(c2), "+f"(c3)
        : "r"(a0), "r"(a1), "r"(a2), "r"(a3), "r"(b0), "r"(b1));
}

// ---------------- lambda ----------------
__global__ void lambda_kernel(const float* __restrict__ lq1, const float* __restrict__ lq2,
                              const float* __restrict__ lk1, const float* __restrict__ lk2) {
    int l = threadIdx.x;
    float s1 = lq1[l] * lk1[l];
    float s2 = lq2[l] * lk2[l];
    #pragma unroll
    for (int o = 16; o; o >>= 1) {
        s1 += __shfl_xor_sync(0xffffffffu, s1, o);
        s2 += __shfl_xor_sync(0xffffffffu, s2, o);
    }
    if (l == 0) g_lambda = expf(s1) - expf(s2) + LAMBDA_INIT_F;
}

// ---------------- weight convert: fp32 [N,K] -> bf16 [N,3K] = [hi|hi|lo] -----
__global__ void convert_w_kernel(const float* __restrict__ src, __nv_bfloat16* __restrict__ dst,
                                 int total, int kshift) {
    int idx = blockIdx.x * 256 + threadIdx.x;
    if (idx >= total) return;
    int Kd = 1 << kshift;
    int row = idx >> kshift;
    int col = idx & (Kd - 1);
    float v = src[idx];
    __nv_bfloat16 hi = __float2bfloat16(v);
    __nv_bfloat16 lo = __float2bfloat16(v - __bfloat162float(hi));
    size_t rb = (size_t)row * 3 * Kd;
    dst[rb + col]          = hi;
    dst[rb + Kd + col]     = hi;
    dst[rb + 2 * Kd + col] = lo;
}

// ---------------- LayerNorm: fp32 in -> bf16 [row,3*DMODEL] = [hi|lo|hi] -----
__global__ __launch_bounds__(256) void ln_kernel(const float* __restrict__ X,
                                                 const float* __restrict__ G,
                                                 const float* __restrict__ Bb,
                                                 __nv_bfloat16* __restrict__ Y) {
    size_t row = blockIdx.x;
    int t = threadIdx.x;
    const float4 v = ((const float4*)(X + row * DMODEL))[t];
    float s  = v.x + v.y + v.z + v.w;
    float ss = v.x * v.x + v.y * v.y + v.z * v.z + v.w * v.w;
    #pragma unroll
    for (int o = 16; o; o >>= 1) {
        s  += __shfl_xor_sync(0xffffffffu, s,  o);
        ss += __shfl_xor_sync(0xffffffffu, ss, o);
    }
    __shared__ float sh_s[8], sh_ss[8];
    int w = t >> 5, l = t & 31;
    if (l == 0) { sh_s[w] = s; sh_ss[w] = ss; }
    __syncthreads();
    if (w == 0) {
        float a  = (l < 8) ? sh_s[l]  : 0.0f;
        float bq = (l < 8) ? sh_ss[l] : 0.0f;
        #pragma unroll
        for (int o = 4; o; o >>= 1) {
            a  += __shfl_xor_sync(0xffffffffu, a,  o);
            bq += __shfl_xor_sync(0xffffffffu, bq, o);
        }
        if (l == 0) { sh_s[0] = a; sh_ss[0] = bq; }
    }
    __syncthreads();
    float mu  = sh_s[0] * (1.0f / DMODEL);
    float var = sh_ss[0] * (1.0f / DMODEL) - mu * mu;
    float inv = rsqrtf(var + 1e-5f);
    const float4 gg = ((const float4*)G)[t];
    const float4 bb = ((const float4*)Bb)[t];
    float o0 = (v.x - mu) * inv * gg.x + bb.x;
    float o1 = (v.y - mu) * inv * gg.y + bb.y;
    float o2 = (v.z - mu) * inv * gg.z + bb.z;
    float o3 = (v.w - mu) * inv * gg.w + bb.w;
    __nv_bfloat16* yr = Y + row * (size_t)(3 * DMODEL) + t * 4;
    __nv_bfloat162 h01, h23, l01, l23;
    h01.x = __float2bfloat16(o0); h01.y = __float2bfloat16(o1);
    h23.x = __float2bfloat16(o2); h23.y = __float2bfloat16(o3);
    l01.x = __float2bfloat16(o0 - __bfloat162float(h01.x));
    l01.y = __float2bfloat16(o1 - __bfloat162float(h01.y));
    l23.x = __float2bfloat16(o2 - __bfloat162float(h23.x));
    l23.y = __float2bfloat16(o3 - __bfloat162float(h23.y));
    *(__nv_bfloat162*)(yr)                  = h01;
    *(__nv_bfloat162*)(yr + 2)              = h23;
    *(__nv_bfloat162*)(yr + DMODEL)         = l01;
    *(__nv_bfloat162*)(yr + DMODEL + 2)     = l23;
    *(__nv_bfloat162*)(yr + 2 * DMODEL)     = h01;
    *(__nv_bfloat162*)(yr + 2 * DMODEL + 2) = h23;
}

// ---------------- per-token differential attention (fp32 in, bf16 3-seg out) -
__global__ __launch_bounds__(64) void attn_kernel(const float* __restrict__ Q,
                                                  const float* __restrict__ K,
                                                  const float* __restrict__ V,
                                                  __nv_bfloat16* __restrict__ O) {
    __shared__ float s_q[2][32][33];
    __shared__ float s_k[2][32][32];
    __shared__ float s_v[2][16][64];
    const int warp = threadIdx.x >> 5;
    const int lane = threadIdx.x & 31;
    const size_t t = (size_t)blockIdx.x * 2 + warp;
    const float* q = Q + t * DMODEL;
    const float* k = K + t * DMODEL;
    const float* v = V + t * DMODEL;
    float (*qs)[33] = s_q[warp];
    float (*ks)[32] = s_k[warp];
    float (*vs)[64] = s_v[warp];

    for (int idx = lane; idx < DMODEL; idx += 32) {
        int h = idx >> 6, r = idx & 63;
        int dd = r >> 1, j = r & 1;
        qs[j * 16 + h][dd] = q[idx] * QSCALE;
        ks[j * 16 + h][dd] = k[idx];
        ((float*)vs)[idx]  = v[idx];
    }
    __syncwarp();
    float qr[32];
    #pragma unroll
    for (int d = 0; d < 32; d++) qr[d] = qs[lane][d];
    float p[32];
    #pragma unroll
    for (int j = 0; j < 32; j++) {
        float s = 0.0f;
        #pragma unroll
        for (int d = 0; d < 32; d++) s += qr[d] * ks[j][d];
        p[j] = s;
    }
    float mx = p[0];
    #pragma unroll
    for (int j = 1; j < 32; j++) mx = fmaxf(mx, p[j]);
    float sum = 0.0f;
    #pragma unroll
    for (int j = 0; j < 32; j++) { p[j] = expf(p[j] - mx); sum += p[j]; }
    float rinv = 1.0f / sum;
    __syncwarp();
    #pragma unroll
    for (int j = 0; j < 32; j++) qs[lane][j] = p[j] * rinv;
    __syncwarp();

    const float lam = g_lambda;
    const int a = lane & 15;
    const int half = lane >> 4;
    float accv[32];
    #pragma unroll
    for (int e = 0; e < 32; e++) accv[e] = 0.0f;
    #pragma unroll
    for (int h = 0; h < 16; h++) {
        float w = qs[a][h] - lam * qs[16 + a][16 + h];
        const float* vrow = &vs[h][half * 32];
        #pragma unroll
        for (int e = 0; e < 32; e++) accv[e] += w * vrow[e];
    }
    float ss = 0.0f;
    #pragma unroll
    for (int e = 0; e < 32; e++) ss += accv[e] * accv[e];
    ss += __shfl_xor_sync(0xffffffffu, ss, 16);
    float scale = rsqrtf(ss * (1.0f / 64.0f) + 1e-5f) * ONE_MINUS_LAMBDA_F;

    __nv_bfloat16* o = O + t * (size_t)(3 * DMODEL) + a * 64 + half * 32;
    #pragma unroll
    for (int e = 0; e < 32; e += 2) {
        float w0 = accv[e] * scale, w1 = accv[e + 1] * scale;
        __nv_bfloat162 hh, ll;
        hh.x = __float2bfloat16(w0); hh.y = __float2bfloat16(w1);
        ll.x = __float2bfloat16(w0 - __bfloat162float(hh.x));
        ll.y = __float2bfloat16(w1 - __bfloat162float(hh.y));
        *(__nv_bfloat162*)(o + e)              = hh;
        *(__nv_bfloat162*)(o + DMODEL + e)     = ll;
        *(__nv_bfloat162*)(o + 2 * DMODEL + e) = hh;
    }
}

// ---------------- HMMA GEMM: C[M,N] = A[M,Kp] @ W[N,Kp]^T (bf16, fp32 acc) ---
// 128x128 tile, BK=64, 256 threads (8 warps, 2m x 4n, warp tile 64x32),
// double-buffered cp.async. Smem rows padded to 72 elems (144 B).
// EPI: 1=bias 2=relu 4=+res(fp32) 8=bf16 3-seg out (else fp32 out)
#define APITCH 144u               // bytes per smem row (72 bf16)
#define ATILE  18432u             // 128 * 144
#define STG    36864u             // A + B
#define GSMEM  73728              // 2 stages

template <int EPI>
__global__ __launch_bounds__(256, 1)
void mma_gemm(const __nv_bfloat16* __restrict__ A, const __nv_bfloat16* __restrict__ W,
              const float* __restrict__ bias, const float* __restrict__ res,
              float* __restrict__ C, __nv_bfloat16* __restrict__ Cbf, int Nn, int Kp) {
    extern __shared__ __align__(1024) char smem[];
    const uint32_t sb = smem_u32(smem);
    const int tid = threadIdx.x;
    const int wid = tid >> 5, lane = tid & 31;
    const int m0 = blockIdx.y * 128, n0 = blockIdx.x * 128;
    const int wm = wid & 1, wn = wid >> 1;
    const int nk = Kp >> 6;

    const __nv_bfloat16* srcA = A + (size_t)m0 * Kp;
    const __nv_bfloat16* srcW = W + (size_t)n0 * Kp;

    // per-thread cp.async offsets
    const int ldrow0 = tid >> 3;          // 0..31 (x4 iters -> 128 rows)
    const int ldseg  = tid & 7;
    const uint32_t ldoff0 = (uint32_t)(ldrow0 * 144 + ldseg * 16);

    // ldmatrix per-lane addresses (byte offsets within tile)
    const int lr = lane & 7, grp = lane >> 3;
    uint32_t aOff[4], bOff[2];
    #pragma unroll
    for (int mi = 0; mi < 4; mi++)
        aOff[mi] = (uint32_t)((wm * 64 + mi * 16 + lr + (grp & 1) * 8) * 144 +
                              ((grp >> 1) * 8) * 2);
    #pragma unroll
    for (int nj = 0; nj < 2; nj++)
        bOff[nj] = ATILE + (uint32_t)((wn * 32 + nj * 16 + lr + (grp >> 1) * 8) * 144 +
                                      ((grp & 1) * 8) * 2);

    float acc[4][4][4];
    #pragma unroll
    for (int i = 0; i < 4; i++)
        #pragma unroll
        for (int j = 0; j < 4; j++)
            #pragma unroll
            for (int e = 0; e < 4; e++) acc[i][j][e] = 0.0f;

    auto load_stage = [&](int kt, int buf) {
        uint32_t base = sb + (uint32_t)buf * STG;
        const __nv_bfloat16* a0 = srcA + kt * 64;
        const __nv_bfloat16* w0 = srcW + kt * 64;
        #pragma unroll
        for (int i = 0; i < 4; i++) {
            int row = ldrow0 + i * 32;
            uint32_t off = ldoff0 + (uint32_t)(i * 32 * 144);
            cpasync16(base + off,         a0 + (size_t)row * Kp + ldseg * 8);
            cpasync16(base + ATILE + off, w0 + (size_t)row * Kp + ldseg * 8);
        }
        CP_COMMIT();
    };

    load_stage(0, 0);
    for (int kt = 0; kt < nk; kt++) {
        int buf = kt & 1;
        if (kt + 1 < nk) { load_stage(kt + 1, buf ^ 1); CP_WAIT1(); }
        else             { CP_WAIT0(); }
        __syncthreads();
        uint32_t base = sb + (uint32_t)buf * STG;
        #pragma unroll
        for (int ks = 0; ks < 4; ks++) {
            uint32_t afr[4][4];
            #pragma unroll
            for (int mi = 0; mi < 4; mi++)
                LDMX4(afr[mi], base + aOff[mi] + ks * 32);
            uint32_t bfr[4][2];
            #pragma unroll
            for (int nj = 0; nj < 2; nj++) {
                uint32_t tmp[4];
                LDMX4(tmp, base + bOff[nj] + ks * 32);
                bfr[2 * nj][0] = tmp[0];     bfr[2 * nj][1] = tmp[1];
                bfr[2 * nj + 1][0] = tmp[2]; bfr[2 * nj + 1][1] = tmp[3];
            }
            #pragma unroll
            for (int mi = 0; mi < 4; mi++)
                #pragma unroll
                for (int ni = 0; ni < 4; ni++)
                    mma16816(acc[mi][ni][0], acc[mi][ni][1], acc[mi][ni][2], acc[mi][ni][3],
                             afr[mi][0], afr[mi][1], afr[mi][2], afr[mi][3],
                             bfr[ni][0], bfr[ni][1]);
        }
        __syncthreads();
    }

    // epilogue
    const int gm = m0 + wm * 64;
    const int gn = n0 + wn * 32;
    const int rr = lane >> 2;
    const int cc = (lane & 3) * 2;
    #pragma unroll
    for (int mi = 0; mi < 4; mi++) {
        #pragma unroll
        for (int ni = 0; ni < 4; ni++) {
            int col = gn + ni * 8 + cc;
            float2 bv = make_float2(0.f, 0.f);
            if (EPI & 1) bv = *(const float2*)(bias + col);
            #pragma unroll
            for (int hh = 0; hh < 2; hh++) {
                int row = gm + mi * 16 + rr + hh * 8;
                float v0 = acc[mi][ni][2 * hh];
                float v1 = acc[mi][ni][2 * hh + 1];
                if (EPI & 1) { v0 += bv.x; v1 += bv.y; }
                if (EPI & 2) { v0 = fmaxf(v0, 0.0f); v1 = fmaxf(v1, 0.0f); }
                if (EPI & 4) {
                    float2 r2 = *(const float2*)(res + (size_t)row * Nn + col);
                    v0 += r2.x; v1 += r2.y;
                }
                if (EPI & 8) {
                    __nv_bfloat16* pr = Cbf + (size_t)row * (3 * Nn) + col;
                    __nv_bfloat162 h2, l2;
                    h2.x = __float2bfloat16(v0);
                    h2.y = __float2bfloat16(v1);
                    l2.x = __float2bfloat16(v0 - __bfloat162float(h2.x));
                    l2.y = __float2bfloat16(v1 - __bfloat162float(h2.y));
                    *(__nv_bfloat162*)(pr)          = h2;
                    *(__nv_bfloat162*)(pr + Nn)     = l2;
                    *(__nv_bfloat162*)(pr + 2 * Nn) = h2;
                } else {
                    *(float2*)(C + (size_t)row * Nn + col) = make_float2(v0, v1);
                }
            }
        }
    }
}

// ---------------- launch ----------------
extern "C" void kernel_launch(void* const* d_in, const int* in_sizes, int n_in,
                              void* d_out, int out_size) {
    const float* x    = (const float*)d_in[0];
    const float* Wq   = (const float*)d_in[1];
    const float* Wk   = (const float*)d_in[2];
    const float* Wv   = (const float*)d_in[3];
    const float* lq1  = (const float*)d_in[4];
    const float* lq2  = (const float*)d_in[5];
    const float* lk1  = (const float*)d_in[6];
    const float* lk2  = (const float*)d_in[7];
    const float* Wo   = (const float*)d_in[8];
    const float* bo   = (const float*)d_in[9];
    const float* ln1g = (const float*)d_in[10];
    const float* ln1b = (const float*)d_in[11];
    const float* ln2g = (const float*)d_in[12];
    const float* ln2b = (const float*)d_in[13];
    const float* W1   = (const float*)d_in[14];
    const float* b1   = (const float*)d_in[15];
    const float* W2   = (const float*)d_in[16];
    const float* b2   = (const float*)d_in[17];
    float* out = (float*)d_out;

    __nv_bfloat16 *phbf, *pattnbf, *ph2bf, *pffnbf, *pwq, *pwk, *pwv, *pwo, *pw1, *pw2;
    float *pq, *pk, *pv, *pconn;
    cudaGetSymbolAddress((void**)&phbf,    g_hbf);
    cudaGetSymbolAddress((void**)&pq,      g_q);
    cudaGetSymbolAddress((void**)&pk,      g_k);
    cudaGetSymbolAddress((void**)&pv,      g_v);
    cudaGetSymbolAddress((void**)&pattnbf, g_attnbf);
    cudaGetSymbolAddress((void**)&pconn,   g_conn);
    cudaGetSymbolAddress((void**)&ph2bf,   g_h2bf);
    cudaGetSymbolAddress((void**)&pffnbf,  g_ffnbf);
    cudaGetSymbolAddress((void**)&pwq,     g_wq);
    cudaGetSymbolAddress((void**)&pwk,     g_wk);
    cudaGetSymbolAddress((void**)&pwv,     g_wv);
    cudaGetSymbolAddress((void**)&pwo,     g_wo);
    cudaGetSymbolAddress((void**)&pw1,     g_w1);
    cudaGetSymbolAddress((void**)&pw2,     g_w2);

    cudaFuncSetAttribute(mma_gemm<0>,  cudaFuncAttributeMaxDynamicSharedMemorySize, GSMEM);
    cudaFuncSetAttribute(mma_gemm<5>,  cudaFuncAttributeMaxDynamicSharedMemorySize, GSMEM);
    cudaFuncSetAttribute(mma_gemm<11>, cudaFuncAttributeMaxDynamicSharedMemorySize, GSMEM);

    lambda_kernel<<<1, 32>>>(lq1, lq2, lk1, lk2);

    // weight converts (fp32 -> bf16 3-seg)
    int tw = DMODEL * DMODEL;
    convert_w_kernel<<<tw / 256, 256>>>(Wq, pwq, tw, 10);
    convert_w_kernel<<<tw / 256, 256>>>(Wk, pwk, tw, 10);
    convert_w_kernel<<<tw / 256, 256>>>(Wv, pwv, tw, 10);
    convert_w_kernel<<<tw / 256, 256>>>(Wo, pwo, tw, 10);
    int t1 = FFDIM * DMODEL;
    convert_w_kernel<<<t1 / 256, 256>>>(W1, pw1, t1, 10);
    convert_w_kernel<<<t1 / 256, 256>>>(W2, pw2, t1, 12);

    // LN1: x -> hbf
    ln_kernel<<<Mrows, 256>>>(x, ln1g, ln1b, phbf);

    dim3 gq(DMODEL / 128, Mrows / 128);   // (8,128)
    mma_gemm<0><<<gq, 256, GSMEM>>>(phbf, pwq, nullptr, nullptr, pq, nullptr, DMODEL, 3 * DMODEL);
    mma_gemm<0><<<gq, 256, GSMEM>>>(phbf, pwk, nullptr, nullptr, pk, nullptr, DMODEL, 3 * DMODEL);
    mma_gemm<0><<<gq, 256, GSMEM>>>(phbf, pwv, nullptr, nullptr, pv, nullptr, DMODEL, 3 * DMODEL);

    attn_kernel<<<Mrows / 2, 64>>>(pq, pk, pv, pattnbf);

    // conn = x + attn @ Wo^T + bo
    mma_gemm<5><<<gq, 256, GSMEM>>>(pattnbf, pwo, bo, x, pconn, nullptr, DMODEL, 3 * DMODEL);

    // LN2: conn -> h2bf
    ln_kernel<<<Mrows, 256>>>(pconn, ln2g, ln2b, ph2bf);

    // ffn = relu(h2 @ W1^T + b1) -> bf16 3-seg
    dim3 g1(FFDIM / 128, Mrows / 128);    // (32,128)
    mma_gemm<11><<<g1, 256, GSMEM>>>(ph2bf, pw1, b1, nullptr, nullptr, pffnbf, FFDIM, 3 * DMODEL);

    // out = conn + ffn @ W2^T + b2
    mma_gemm<5><<<gq, 256, GSMEM>>>(pffnbf, pw2, b2, pconn, out, nullptr, DMODEL, 3 * FFDIM);
}

// round 5
// speedup vs baseline: 2.6942x; 1.2607x over previous
#include <cuda_runtime.h>
#include <cuda_bf16.h>
#include <cstdint>
#include <cstddef>

#define Mrows   16384
#define DMODEL  1024
#define FFDIM   4096
#define QKVN    3072
#define LAMBDA_INIT_F        0.35550906759096926f
#define ONE_MINUS_LAMBDA_F   0.64449093240903074f
#define QSCALE               0.17677669529663687f

// ---------------- scratch (device globals; no runtime allocs) ----------------
// All split buffers: [rows, 2K] = [hi | lo]
__device__ __align__(256) __nv_bfloat16 g_hbf   [(size_t)Mrows * 2 * DMODEL];
__device__ __align__(256) float         g_qkv   [(size_t)Mrows * QKVN];
__device__ __align__(256) __nv_bfloat16 g_attnbf[(size_t)Mrows * 2 * DMODEL];
__device__ __align__(256) float         g_conn  [(size_t)Mrows * DMODEL];
__device__ __align__(256) __nv_bfloat16 g_h2bf  [(size_t)Mrows * 2 * DMODEL];
__device__ __align__(256) __nv_bfloat16 g_ffnbf [(size_t)Mrows * 2 * FFDIM];
__device__ __align__(256) __nv_bfloat16 g_wqkv  [(size_t)QKVN   * 2 * DMODEL];
__device__ __align__(256) __nv_bfloat16 g_wo    [(size_t)DMODEL * 2 * DMODEL];
__device__ __align__(256) __nv_bfloat16 g_w1    [(size_t)FFDIM  * 2 * DMODEL];
__device__ __align__(256) __nv_bfloat16 g_w2    [(size_t)DMODEL * 2 * FFDIM];
__device__ float g_lambda;

// ---------------- PTX helpers (base sm_103 target; no 'a' features) ----------
__device__ __forceinline__ uint32_t smem_u32(const void* p) {
    uint32_t a;
    asm("{ .reg .u64 t; cvta.to.shared.u64 t, %1; cvt.u32.u64 %0, t; }" : "=r"(a) : "l"(p));
    return a;
}
__device__ __forceinline__ void cpasync16(uint32_t d, const void* g) {
    asm volatile("cp.async.cg.shared.global [%0], [%1], 16;" :: "r"(d), "l"(g));
}
#define CP_COMMIT()  asm volatile("cp.async.commit_group;" ::: "memory")
#define CP_WAIT1()   asm volatile("cp.async.wait_group 1;" ::: "memory")
#define CP_WAIT0()   asm volatile("cp.async.wait_group 0;" ::: "memory")

#define LDMX4(r, addr) \
    asm volatile("ldmatrix.sync.aligned.m8n8.x4.shared.b16 {%0,%1,%2,%3}, [%4];" \
                 : "=r"((r)[0]), "=r"((r)[1]), "=r"((r)[2]), "=r"((r)[3]) : "r"(addr))

__device__ __forceinline__ void mma16816(float& c0, float& c1, float& c2, float& c3,
                                         uint32_t a0, uint32_t a1, uint32_t a2, uint32_t a3,
                                         uint32_t b0, uint32_t b1) {
    asm volatile(
        "mma.sync.aligned.m16n8k16.row.col.f32.bf16.bf16.f32 "
        "{%0,%1,%2,%3}, {%4,%5,%6,%7}, {%8,%9}, {%0,%1,%2,%3};"
        : "+f"(c0), "+f"(c1), "+f"(c2), "+f"(c3)
        : "r"(a0), "r"(a1), "r"(a2), "r"(a3), "r"(b0), "r"(b1));
}

// ---------------- lambda ----------------
__global__ void lambda_kernel(const float* __restrict__ lq1, const float* __restrict__ lq2,
                              const float* __restrict__ lk1, const float* __restrict__ lk2) {
    int l = threadIdx.x;
    float s1 = lq1[l] * lk1[l];
    float s2 = lq2[l] * lk2[l];
    #pragma unroll
    for (int o = 16; o; o >>= 1) {
        s1 += __shfl_xor_sync(0xffffffffu, s1, o);
        s2 += __shfl_xor_sync(0xffffffffu, s2, o);
    }
    if (l == 0) g_lambda = expf(s1) - expf(s2) + LAMBDA_INIT_F;
}

// ---------------- weight convert: fp32 [N,K] -> bf16 [N,2K] = [hi|lo] --------
__global__ void convert_w_kernel(const float* __restrict__ src, __nv_bfloat16* __restrict__ dst,
                                 int total, int kshift) {
    int idx = blockIdx.x * 256 + threadIdx.x;
    if (idx >= total) return;
    int Kd = 1 << kshift;
    int row = idx >> kshift;
    int col = idx & (Kd - 1);
    float v = src[idx];
    __nv_bfloat16 hi = __float2bfloat16(v);
    __nv_bfloat16 lo = __float2bfloat16(v - __bfloat162float(hi));
    size_t rb = ((size_t)row << (kshift + 1));
    dst[rb + col]      = hi;
    dst[rb + Kd + col] = lo;
}

// ---------------- LayerNorm: fp32 in -> bf16 [row, 2*DMODEL] = [hi|lo] -------
__global__ __launch_bounds__(256) void ln_kernel(const float* __restrict__ X,
                                                 const float* __restrict__ G,
                                                 const float* __restrict__ Bb,
                                                 __nv_bfloat16* __restrict__ Y) {
    size_t row = blockIdx.x;
    int t = threadIdx.x;
    const float4 v = ((const float4*)(X + row * DMODEL))[t];
    float s  = v.x + v.y + v.z + v.w;
    float ss = v.x * v.x + v.y * v.y + v.z * v.z + v.w * v.w;
    #pragma unroll
    for (int o = 16; o; o >>= 1) {
        s  += __shfl_xor_sync(0xffffffffu, s,  o);
        ss += __shfl_xor_sync(0xffffffffu, ss, o);
    }
    __shared__ float sh_s[8], sh_ss[8];
    int w = t >> 5, l = t & 31;
    if (l == 0) { sh_s[w] = s; sh_ss[w] = ss; }
    __syncthreads();
    if (w == 0) {
        float a  = (l < 8) ? sh_s[l]  : 0.0f;
        float bq = (l < 8) ? sh_ss[l] : 0.0f;
        #pragma unroll
        for (int o = 4; o; o >>= 1) {
            a  += __shfl_xor_sync(0xffffffffu, a,  o);
            bq += __shfl_xor_sync(0xffffffffu, bq, o);
        }
        if (l == 0) { sh_s[0] = a; sh_ss[0] = bq; }
    }
    __syncthreads();
    float mu  = sh_s[0] * (1.0f / DMODEL);
    float var = sh_ss[0] * (1.0f / DMODEL) - mu * mu;
    float inv = rsqrtf(var + 1e-5f);
    const float4 gg = ((const float4*)G)[t];
    const float4 bb = ((const float4*)Bb)[t];
    float o0 = (v.x - mu) * inv * gg.x + bb.x;
    float o1 = (v.y - mu) * inv * gg.y + bb.y;
    float o2 = (v.z - mu) * inv * gg.z + bb.z;
    float o3 = (v.w - mu) * inv * gg.w + bb.w;
    __nv_bfloat16* yr = Y + row * (size_t)(2 * DMODEL) + t * 4;
    __nv_bfloat162 h01, h23, l01, l23;
    h01.x = __float2bfloat16(o0); h01.y = __float2bfloat16(o1);
    h23.x = __float2bfloat16(o2); h23.y = __float2bfloat16(o3);
    l01.x = __float2bfloat16(o0 - __bfloat162float(h01.x));
    l01.y = __float2bfloat16(o1 - __bfloat162float(h01.y));
    l23.x = __float2bfloat16(o2 - __bfloat162float(h23.x));
    l23.y = __float2bfloat16(o3 - __bfloat162float(h23.y));
    *(__nv_bfloat162*)(yr)              = h01;
    *(__nv_bfloat162*)(yr + 2)          = h23;
    *(__nv_bfloat162*)(yr + DMODEL)     = l01;
    *(__nv_bfloat162*)(yr + DMODEL + 2) = l23;
}

// ---------------- per-token differential attention -------------------------
// QKV fused input: row pitch 3072, q at +0, k at +1024, v at +2048.
__global__ __launch_bounds__(64) void attn_kernel(const float* __restrict__ QKV,
                                                  __nv_bfloat16* __restrict__ O) {
    __shared__ float s_q[2][32][33];
    __shared__ float s_k[2][32][32];
    __shared__ float s_v[2][16][64];
    const int warp = threadIdx.x >> 5;
    const int lane = threadIdx.x & 31;
    const size_t t = (size_t)blockIdx.x * 2 + warp;
    const float* q = QKV + t * QKVN;
    const float* k = q + DMODEL;
    const float* v = k + DMODEL;
    float (*qs)[33] = s_q[warp];
    float (*ks)[32] = s_k[warp];
    float (*vs)[64] = s_v[warp];

    for (int idx = lane; idx < DMODEL; idx += 32) {
        int h = idx >> 6, r = idx & 63;
        int dd = r >> 1, j = r & 1;
        qs[j * 16 + h][dd] = q[idx] * QSCALE;
        ks[j * 16 + h][dd] = k[idx];
        ((float*)vs)[idx]  = v[idx];
    }
    __syncwarp();
    float qr[32];
    #pragma unroll
    for (int d = 0; d < 32; d++) qr[d] = qs[lane][d];
    float p[32];
    #pragma unroll
    for (int j = 0; j < 32; j++) {
        float s = 0.0f;
        #pragma unroll
        for (int d = 0; d < 32; d++) s += qr[d] * ks[j][d];
        p[j] = s;
    }
    float mx = p[0];
    #pragma unroll
    for (int j = 1; j < 32; j++) mx = fmaxf(mx, p[j]);
    float sum = 0.0f;
    #pragma unroll
    for (int j = 0; j < 32; j++) { p[j] = expf(p[j] - mx); sum += p[j]; }
    float rinv = 1.0f / sum;
    __syncwarp();
    #pragma unroll
    for (int j = 0; j < 32; j++) qs[lane][j] = p[j] * rinv;
    __syncwarp();

    const float lam = g_lambda;
    const int a = lane & 15;
    const int half = lane >> 4;
    float accv[32];
    #pragma unroll
    for (int e = 0; e < 32; e++) accv[e] = 0.0f;
    #pragma unroll
    for (int h = 0; h < 16; h++) {
        float w = qs[a][h] - lam * qs[16 + a][16 + h];
        const float* vrow = &vs[h][half * 32];
        #pragma unroll
        for (int e = 0; e < 32; e++) accv[e] += w * vrow[e];
    }
    float ss = 0.0f;
    #pragma unroll
    for (int e = 0; e < 32; e++) ss += accv[e] * accv[e];
    ss += __shfl_xor_sync(0xffffffffu, ss, 16);
    float scale = rsqrtf(ss * (1.0f / 64.0f) + 1e-5f) * ONE_MINUS_LAMBDA_F;

    __nv_bfloat16* o = O + t * (size_t)(2 * DMODEL) + a * 64 + half * 32;
    #pragma unroll
    for (int e = 0; e < 32; e += 2) {
        float w0 = accv[e] * scale, w1 = accv[e + 1] * scale;
        __nv_bfloat162 hh, ll;
        hh.x = __float2bfloat16(w0); hh.y = __float2bfloat16(w1);
        ll.x = __float2bfloat16(w0 - __bfloat162float(hh.x));
        ll.y = __float2bfloat16(w1 - __bfloat162float(hh.y));
        *(__nv_bfloat162*)(o + e)          = hh;
        *(__nv_bfloat162*)(o + DMODEL + e) = ll;
    }
}

// ---------------- HMMA GEMM with register-level hi/lo reuse ------------------
// A:[M,2Ko]=[hi|lo], W:[N,2Ko]=[hi|lo]. C = A@W^T with 3-term split:
// acc += Ahi*Whi + Alo*Whi + Ahi*Wlo  (per k-chunk, fragments loaded once).
// 128x128 tile, BK=64 (original K), 256 threads (8 warps 2m x 4n, 64x32 each),
// double-buffered cp.async. 4 smem tiles/stage (Ahi,Alo,Whi,Wlo), 144B pitch.
// EPI: 1=bias 2=relu 4=+res(fp32) 8=bf16 hi/lo out (else fp32 out)
#define TILE   18432u             // 128 rows * 144 B
#define STG    73728u             // 4 tiles
#define GSMEM  147456             // 2 stages

template <int EPI>
__global__ __launch_bounds__(256, 1)
void mma_gemm(const __nv_bfloat16* __restrict__ A, const __nv_bfloat16* __restrict__ W,
              const float* __restrict__ bias, const float* __restrict__ res,
              float* __restrict__ C, __nv_bfloat16* __restrict__ Cbf, int Nn, int Ko) {
    extern __shared__ __align__(1024) char smem[];
    const uint32_t sb = smem_u32(smem);
    const int tid = threadIdx.x;
    const int wid = tid >> 5, lane = tid & 31;
    const int m0 = blockIdx.y * 128, n0 = blockIdx.x * 128;
    const int wm = wid & 1, wn = wid >> 1;
    const int nk = Ko >> 6;
    const int Kp = 2 * Ko;

    const __nv_bfloat16* srcA = A + (size_t)m0 * Kp;
    const __nv_bfloat16* srcW = W + (size_t)n0 * Kp;

    const int ldrow0 = tid >> 3;          // 0..31 (x4 -> 128 rows)
    const int ldseg  = tid & 7;           // 8 segs x 8 bf16 = 64 cols
    const uint32_t ldoff0 = (uint32_t)(ldrow0 * 144 + ldseg * 16);

    // ldmatrix per-lane offsets (within a tile)
    const int lr = lane & 7, grp = lane >> 3;
    uint32_t aOff[4], bOff[2];
    #pragma unroll
    for (int mi = 0; mi < 4; mi++)
        aOff[mi] = (uint32_t)((wm * 64 + mi * 16 + lr + (grp & 1) * 8) * 144 +
                              ((grp >> 1) * 8) * 2);
    #pragma unroll
    for (int nj = 0; nj < 2; nj++)
        bOff[nj] = (uint32_t)((wn * 32 + nj * 16 + lr + (grp >> 1) * 8) * 144 +
                              ((grp & 1) * 8) * 2);

    float acc[4][4][4];
    #pragma unroll
    for (int i = 0; i < 4; i++)
        #pragma unroll
        for (int j = 0; j < 4; j++)
            #pragma unroll
            for (int e = 0; e < 4; e++) acc[i][j][e] = 0.0f;

    auto load_stage = [&](int kt, int buf) {
        uint32_t base = sb + (uint32_t)buf * STG;
        const __nv_bfloat16* ah = srcA + kt * 64;          // hi cols
        const __nv_bfloat16* al = ah + Ko;                 // lo cols
        const __nv_bfloat16* wh = srcW + kt * 64;
        const __nv_bfloat16* wl = wh + Ko;
        #pragma unroll
        for (int i = 0; i < 4; i++) {
            int row = ldrow0 + i * 32;
            size_t roff = (size_t)row * Kp + ldseg * 8;
            uint32_t off = ldoff0 + (uint32_t)(i * 32 * 144);
            cpasync16(base + off,            ah + roff);
            cpasync16(base + TILE + off,     al + roff);
            cpasync16(base + 2 * TILE + off, wh + roff);
            cpasync16(base + 3 * TILE + off, wl + roff);
        }
        CP_COMMIT();
    };

    load_stage(0, 0);
    for (int kt = 0; kt < nk; kt++) {
        int buf = kt & 1;
        if (kt + 1 < nk) { load_stage(kt + 1, buf ^ 1); CP_WAIT1(); }
        else             { CP_WAIT0(); }
        __syncthreads();
        uint32_t base = sb + (uint32_t)buf * STG;
        #pragma unroll
        for (int ks = 0; ks < 4; ks++) {
            uint32_t ahf[4][4], alf[4][4];
            #pragma unroll
            for (int mi = 0; mi < 4; mi++) {
                LDMX4(ahf[mi], base + aOff[mi] + ks * 32);
                LDMX4(alf[mi], base + TILE + aOff[mi] + ks * 32);
            }
            uint32_t bhf[4][2], blf[4][2];
            #pragma unroll
            for (int nj = 0; nj < 2; nj++) {
                uint32_t th[4], tl[4];
                LDMX4(th, base + 2 * TILE + bOff[nj] + ks * 32);
                LDMX4(tl, base + 3 * TILE + bOff[nj] + ks * 32);
                bhf[2 * nj][0] = th[0];     bhf[2 * nj][1] = th[1];
                bhf[2 * nj + 1][0] = th[2]; bhf[2 * nj + 1][1] = th[3];
                blf[2 * nj][0] = tl[0];     blf[2 * nj][1] = tl[1];
                blf[2 * nj + 1][0] = tl[2]; blf[2 * nj + 1][1] = tl[3];
            }
            #pragma unroll
            for (int mi = 0; mi < 4; mi++)
                #pragma unroll
                for (int ni = 0; ni < 4; ni++) {
                    mma16816(acc[mi][ni][0], acc[mi][ni][1], acc[mi][ni][2], acc[mi][ni][3],
                             ahf[mi][0], ahf[mi][1], ahf[mi][2], ahf[mi][3],
                             bhf[ni][0], bhf[ni][1]);
                    mma16816(acc[mi][ni][0], acc[mi][ni][1], acc[mi][ni][2], acc[mi][ni][3],
                             alf[mi][0], alf[mi][1], alf[mi][2], alf[mi][3],
                             bhf[ni][0], bhf[ni][1]);
                    mma16816(acc[mi][ni][0], acc[mi][ni][1], acc[mi][ni][2], acc[mi][ni][3],
                             ahf[mi][0], ahf[mi][1], ahf[mi][2], ahf[mi][3],
                             blf[ni][0], blf[ni][1]);
                }
        }
        __syncthreads();
    }

    // epilogue
    const int gm = m0 + wm * 64;
    const int gn = n0 + wn * 32;
    const int rr = lane >> 2;
    const int cc = (lane & 3) * 2;
    #pragma unroll
    for (int mi = 0; mi < 4; mi++) {
        #pragma unroll
        for (int ni = 0; ni < 4; ni++) {
            int col = gn + ni * 8 + cc;
            float2 bv = make_float2(0.f, 0.f);
            if (EPI & 1) bv = *(const float2*)(bias + col);
            #pragma unroll
            for (int hh = 0; hh < 2; hh++) {
                int row = gm + mi * 16 + rr + hh * 8;
                float v0 = acc[mi][ni][2 * hh];
                float v1 = acc[mi][ni][2 * hh + 1];
                if (EPI & 1) { v0 += bv.x; v1 += bv.y; }
                if (EPI & 2) { v0 = fmaxf(v0, 0.0f); v1 = fmaxf(v1, 0.0f); }
                if (EPI & 4) {
                    float2 r2 = *(const float2*)(res + (size_t)row * Nn + col);
                    v0 += r2.x; v1 += r2.y;
                }
                if (EPI & 8) {
                    __nv_bfloat16* pr = Cbf + (size_t)row * (2 * Nn) + col;
                    __nv_bfloat162 h2, l2;
                    h2.x = __float2bfloat16(v0);
                    h2.y = __float2bfloat16(v1);
                    l2.x = __float2bfloat16(v0 - __bfloat162float(h2.x));
                    l2.y = __float2bfloat16(v1 - __bfloat162float(h2.y));
                    *(__nv_bfloat162*)(pr)      = h2;
                    *(__nv_bfloat162*)(pr + Nn) = l2;
                } else {
                    *(float2*)(C + (size_t)row * Nn + col) = make_float2(v0, v1);
                }
            }
        }
    }
}

// ---------------- launch ----------------
extern "C" void kernel_launch(void* const* d_in, const int* in_sizes, int n_in,
                              void* d_out, int out_size) {
    const float* x    = (const float*)d_in[0];
    const float* Wq   = (const float*)d_in[1];
    const float* Wk   = (const float*)d_in[2];
    const float* Wv   = (const float*)d_in[3];
    const float* lq1  = (const float*)d_in[4];
    const float* lq2  = (const float*)d_in[5];
    const float* lk1  = (const float*)d_in[6];
    const float* lk2  = (const float*)d_in[7];
    const float* Wo   = (const float*)d_in[8];
    const float* bo   = (const float*)d_in[9];
    const float* ln1g = (const float*)d_in[10];
    const float* ln1b = (const float*)d_in[11];
    const float* ln2g = (const float*)d_in[12];
    const float* ln2b = (const float*)d_in[13];
    const float* W1   = (const float*)d_in[14];
    const float* b1   = (const float*)d_in[15];
    const float* W2   = (const float*)d_in[16];
    const float* b2   = (const float*)d_in[17];
    float* out = (float*)d_out;

    __nv_bfloat16 *phbf, *pattnbf, *ph2bf, *pffnbf, *pwqkv, *pwo, *pw1, *pw2;
    float *pqkv, *pconn;
    cudaGetSymbolAddress((void**)&phbf,    g_hbf);
    cudaGetSymbolAddress((void**)&pqkv,    g_qkv);
    cudaGetSymbolAddress((void**)&pattnbf, g_attnbf);
    cudaGetSymbolAddress((void**)&pconn,   g_conn);
    cudaGetSymbolAddress((void**)&ph2bf,   g_h2bf);
    cudaGetSymbolAddress((void**)&pffnbf,  g_ffnbf);
    cudaGetSymbolAddress((void**)&pwqkv,   g_wqkv);
    cudaGetSymbolAddress((void**)&pwo,     g_wo);
    cudaGetSymbolAddress((void**)&pw1,     g_w1);
    cudaGetSymbolAddress((void**)&pw2,     g_w2);

    cudaFuncSetAttribute(mma_gemm<0>,  cudaFuncAttributeMaxDynamicSharedMemorySize, GSMEM);
    cudaFuncSetAttribute(mma_gemm<5>,  cudaFuncAttributeMaxDynamicSharedMemorySize, GSMEM);
    cudaFuncSetAttribute(mma_gemm<11>, cudaFuncAttributeMaxDynamicSharedMemorySize, GSMEM);

    lambda_kernel<<<1, 32>>>(lq1, lq2, lk1, lk2);

    // weight converts (fp32 -> bf16 hi|lo); Q,K,V stacked into one [3072, 2048]
    int tw = DMODEL * DMODEL;
    convert_w_kernel<<<tw / 256, 256>>>(Wq, pwqkv,                               tw, 10);
    convert_w_kernel<<<tw / 256, 256>>>(Wk, pwqkv + (size_t)DMODEL * 2 * DMODEL, tw, 10);
    convert_w_kernel<<<tw / 256, 256>>>(Wv, pwqkv + (size_t)2 * DMODEL * 2 * DMODEL, tw, 10);
    convert_w_kernel<<<tw / 256, 256>>>(Wo, pwo, tw, 10);
    int t1 = FFDIM * DMODEL;
    convert_w_kernel<<<t1 / 256, 256>>>(W1, pw1, t1, 10);
    convert_w_kernel<<<t1 / 256, 256>>>(W2, pw2, t1, 12);

    // LN1: x -> hbf
    ln_kernel<<<Mrows, 256>>>(x, ln1g, ln1b, phbf);

    // fused QKV: [M,1024] x [3072,1024]^T -> [M,3072]
    dim3 gqkv(QKVN / 128, Mrows / 128);   // (24,128)
    mma_gemm<0><<<gqkv, 256, GSMEM>>>(phbf, pwqkv, nullptr, nullptr, pqkv, nullptr, QKVN, DMODEL);

    attn_kernel<<<Mrows / 2, 64>>>(pqkv, pattnbf);

    // conn = x + attn @ Wo^T + bo
    dim3 gq(DMODEL / 128, Mrows / 128);   // (8,128)
    mma_gemm<5><<<gq, 256, GSMEM>>>(pattnbf, pwo, bo, x, pconn, nullptr, DMODEL, DMODEL);

    // LN2: conn -> h2bf
    ln_kernel<<<Mrows, 256>>>(pconn, ln2g, ln2b, ph2bf);

    // ffn = relu(h2 @ W1^T + b1) -> bf16 hi|lo
    dim3 g1(FFDIM / 128, Mrows / 128);    // (32,128)
    mma_gemm<11><<<g1, 256, GSMEM>>>(ph2bf, pw1, b1, nullptr, nullptr, pffnbf, FFDIM, DMODEL);

    // out = conn + ffn @ W2^T + b2
    mma_gemm<5><<<gq, 256, GSMEM>>>(pffnbf, pw2, b2, pconn, out, nullptr, DMODEL, FFDIM);
}

// round 6
// speedup vs baseline: 2.7113x; 1.0063x over previous
#include <cuda_runtime.h>
#include <cuda_bf16.h>
#include <cstdint>
#include <cstddef>

#define Mrows   16384
#define DMODEL  1024
#define FFDIM   4096
#define QKVN    3072
#define LAMBDA_INIT_F        0.35550906759096926f
#define ONE_MINUS_LAMBDA_F   0.64449093240903074f
#define QSCALE               0.17677669529663687f

// ---------------- scratch (device globals; no runtime allocs) ----------------
// All split buffers: [rows, 2K] = [hi | lo]
__device__ __align__(256) __nv_bfloat16 g_hbf   [(size_t)Mrows * 2 * DMODEL];
__device__ __align__(256) float         g_qkv   [(size_t)Mrows * QKVN];
__device__ __align__(256) __nv_bfloat16 g_attnbf[(size_t)Mrows * 2 * DMODEL];
__device__ __align__(256) float         g_conn  [(size_t)Mrows * DMODEL];
__device__ __align__(256) __nv_bfloat16 g_h2bf  [(size_t)Mrows * 2 * DMODEL];
__device__ __align__(256) __nv_bfloat16 g_ffnbf [(size_t)Mrows * 2 * FFDIM];
__device__ __align__(256) __nv_bfloat16 g_wqkv  [(size_t)QKVN   * 2 * DMODEL];
__device__ __align__(256) __nv_bfloat16 g_wo    [(size_t)DMODEL * 2 * DMODEL];
__device__ __align__(256) __nv_bfloat16 g_w1    [(size_t)FFDIM  * 2 * DMODEL];
__device__ __align__(256) __nv_bfloat16 g_w2    [(size_t)DMODEL * 2 * FFDIM];
__device__ float g_lambda;

// ---------------- PTX helpers (base sm_103 target; no 'a' features) ----------
__device__ __forceinline__ uint32_t smem_u32(const void* p) {
    uint32_t a;
    asm("{ .reg .u64 t; cvta.to.shared.u64 t, %1; cvt.u32.u64 %0, t; }" : "=r"(a) : "l"(p));
    return a;
}
__device__ __forceinline__ void cpasync16(uint32_t d, const void* g) {
    asm volatile("cp.async.cg.shared.global [%0], [%1], 16;" :: "r"(d), "l"(g));
}
#define CP_COMMIT()  asm volatile("cp.async.commit_group;" ::: "memory")
#define CP_WAIT1()   asm volatile("cp.async.wait_group 1;" ::: "memory")
#define CP_WAIT0()   asm volatile("cp.async.wait_group 0;" ::: "memory")

#define LDMX4(r, addr) \
    asm volatile("ldmatrix.sync.aligned.m8n8.x4.shared.b16 {%0,%1,%2,%3}, [%4];" \
                 : "=r"((r)[0]), "=r"((r)[1]), "=r"((r)[2]), "=r"((r)[3]) : "r"(addr))

__device__ __forceinline__ void mma16816(float& c0, float& c1, float& c2, float& c3,
                                         uint32_t a0, uint32_t a1, uint32_t a2, uint32_t a3,
                                         uint32_t b0, uint32_t b1) {
    asm volatile(
        "mma.sync.aligned.m16n8k16.row.col.f32.bf16.bf16.f32 "
        "{%0,%1,%2,%3}, {%4,%5,%6,%7}, {%8,%9}, {%0,%1,%2,%3};"
        : "+f"(c0), "+f"(c1), "+f"(c2), "+f"(c3)
        : "r"(a0), "r"(a1), "r"(a2), "r"(a3), "r"(b0), "r"(b1));
}

// ---------------- lambda ----------------
__global__ void lambda_kernel(const float* __restrict__ lq1, const float* __restrict__ lq2,
                              const float* __restrict__ lk1, const float* __restrict__ lk2) {
    int l = threadIdx.x;
    float s1 = lq1[l] * lk1[l];
    float s2 = lq2[l] * lk2[l];
    #pragma unroll
    for (int o = 16; o; o >>= 1) {
        s1 += __shfl_xor_sync(0xffffffffu, s1, o);
        s2 += __shfl_xor_sync(0xffffffffu, s2, o);
    }
    if (l == 0) g_lambda = expf(s1) - expf(s2) + LAMBDA_INIT_F;
}

// ---------------- weight convert: fp32 [N,K] -> bf16 [N,2K] = [hi|lo] --------
__global__ void convert_w_kernel(const float* __restrict__ src, __nv_bfloat16* __restrict__ dst,
                                 int total, int kshift) {
    int idx = blockIdx.x * 256 + threadIdx.x;
    if (idx >= total) return;
    int Kd = 1 << kshift;
    int row = idx >> kshift;
    int col = idx & (Kd - 1);
    float v = src[idx];
    __nv_bfloat16 hi = __float2bfloat16(v);
    __nv_bfloat16 lo = __float2bfloat16(v - __bfloat162float(hi));
    size_t rb = ((size_t)row << (kshift + 1));
    dst[rb + col]      = hi;
    dst[rb + Kd + col] = lo;
}

// ---------------- LayerNorm: fp32 in -> bf16 [row, 2*DMODEL] = [hi|lo] -------
__global__ __launch_bounds__(256) void ln_kernel(const float* __restrict__ X,
                                                 const float* __restrict__ G,
                                                 const float* __restrict__ Bb,
                                                 __nv_bfloat16* __restrict__ Y) {
    size_t row = blockIdx.x;
    int t = threadIdx.x;
    const float4 v = ((const float4*)(X + row * DMODEL))[t];
    float s  = v.x + v.y + v.z + v.w;
    float ss = v.x * v.x + v.y * v.y + v.z * v.z + v.w * v.w;
    #pragma unroll
    for (int o = 16; o; o >>= 1) {
        s  += __shfl_xor_sync(0xffffffffu, s,  o);
        ss += __shfl_xor_sync(0xffffffffu, ss, o);
    }
    __shared__ float sh_s[8], sh_ss[8];
    int w = t >> 5, l = t & 31;
    if (l == 0) { sh_s[w] = s; sh_ss[w] = ss; }
    __syncthreads();
    if (w == 0) {
        float a  = (l < 8) ? sh_s[l]  : 0.0f;
        float bq = (l < 8) ? sh_ss[l] : 0.0f;
        #pragma unroll
        for (int o = 4; o; o >>= 1) {
            a  += __shfl_xor_sync(0xffffffffu, a,  o);
            bq += __shfl_xor_sync(0xffffffffu, bq, o);
        }
        if (l == 0) { sh_s[0] = a; sh_ss[0] = bq; }
    }
    __syncthreads();
    float mu  = sh_s[0] * (1.0f / DMODEL);
    float var = sh_ss[0] * (1.0f / DMODEL) - mu * mu;
    float inv = rsqrtf(var + 1e-5f);
    const float4 gg = ((const float4*)G)[t];
    const float4 bb = ((const float4*)Bb)[t];
    float o0 = (v.x - mu) * inv * gg.x + bb.x;
    float o1 = (v.y - mu) * inv * gg.y + bb.y;
    float o2 = (v.z - mu) * inv * gg.z + bb.z;
    float o3 = (v.w - mu) * inv * gg.w + bb.w;
    __nv_bfloat16* yr = Y + row * (size_t)(2 * DMODEL) + t * 4;
    __nv_bfloat162 h01, h23, l01, l23;
    h01.x = __float2bfloat16(o0); h01.y = __float2bfloat16(o1);
    h23.x = __float2bfloat16(o2); h23.y = __float2bfloat16(o3);
    l01.x = __float2bfloat16(o0 - __bfloat162float(h01.x));
    l01.y = __float2bfloat16(o1 - __bfloat162float(h01.y));
    l23.x = __float2bfloat16(o2 - __bfloat162float(h23.x));
    l23.y = __float2bfloat16(o3 - __bfloat162float(h23.y));
    *(__nv_bfloat162*)(yr)              = h01;
    *(__nv_bfloat162*)(yr + 2)          = h23;
    *(__nv_bfloat162*)(yr + DMODEL)     = l01;
    *(__nv_bfloat162*)(yr + DMODEL + 2) = l23;
}

// ---------------- per-token differential attention -------------------------
// QKV fused input: row pitch 3072, q at +0, k at +1024, v at +2048.
__global__ __launch_bounds__(64) void attn_kernel(const float* __restrict__ QKV,
                                                  __nv_bfloat16* __restrict__ O) {
    __shared__ float s_q[2][32][33];
    __shared__ float s_k[2][32][32];
    __shared__ float s_v[2][16][64];
    const int warp = threadIdx.x >> 5;
    const int lane = threadIdx.x & 31;
    const size_t t = (size_t)blockIdx.x * 2 + warp;
    const float* q = QKV + t * QKVN;
    const float* k = q + DMODEL;
    const float* v = k + DMODEL;
    float (*qs)[33] = s_q[warp];
    float (*ks)[32] = s_k[warp];
    float (*vs)[64] = s_v[warp];

    for (int idx = lane; idx < DMODEL; idx += 32) {
        int h = idx >> 6, r = idx & 63;
        int dd = r >> 1, j = r & 1;
        qs[j * 16 + h][dd] = q[idx] * QSCALE;
        ks[j * 16 + h][dd] = k[idx];
        ((float*)vs)[idx]  = v[idx];
    }
    __syncwarp();
    float qr[32];
    #pragma unroll
    for (int d = 0; d < 32; d++) qr[d] = qs[lane][d];
    float p[32];
    #pragma unroll
    for (int j = 0; j < 32; j++) {
        float s = 0.0f;
        #pragma unroll
        for (int d = 0; d < 32; d++) s += qr[d] * ks[j][d];
        p[j] = s;
    }
    float mx = p[0];
    #pragma unroll
    for (int j = 1; j < 32; j++) mx = fmaxf(mx, p[j]);
    float sum = 0.0f;
    #pragma unroll
    for (int j = 0; j < 32; j++) { p[j] = expf(p[j] - mx); sum += p[j]; }
    float rinv = 1.0f / sum;
    __syncwarp();
    #pragma unroll
    for (int j = 0; j < 32; j++) qs[lane][j] = p[j] * rinv;
    __syncwarp();

    const float lam = g_lambda;
    const int a = lane & 15;
    const int half = lane >> 4;
    float accv[32];
    #pragma unroll
    for (int e = 0; e < 32; e++) accv[e] = 0.0f;
    #pragma unroll
    for (int h = 0; h < 16; h++) {
        float w = qs[a][h] - lam * qs[16 + a][16 + h];
        const float* vrow = &vs[h][half * 32];
        #pragma unroll
        for (int e = 0; e < 32; e++) accv[e] += w * vrow[e];
    }
    float ss = 0.0f;
    #pragma unroll
    for (int e = 0; e < 32; e++) ss += accv[e] * accv[e];
    ss += __shfl_xor_sync(0xffffffffu, ss, 16);
    float scale = rsqrtf(ss * (1.0f / 64.0f) + 1e-5f) * ONE_MINUS_LAMBDA_F;

    __nv_bfloat16* o = O + t * (size_t)(2 * DMODEL) + a * 64 + half * 32;
    #pragma unroll
    for (int e = 0; e < 32; e += 2) {
        float w0 = accv[e] * scale, w1 = accv[e + 1] * scale;
        __nv_bfloat162 hh, ll;
        hh.x = __float2bfloat16(w0); hh.y = __float2bfloat16(w1);
        ll.x = __float2bfloat16(w0 - __bfloat162float(hh.x));
        ll.y = __float2bfloat16(w1 - __bfloat162float(hh.y));
        *(__nv_bfloat162*)(o + e)          = hh;
        *(__nv_bfloat162*)(o + DMODEL + e) = ll;
    }
}

// ---------------- HMMA GEMM, 128x256 tile, warp tile 64x64 -------------------
// A:[M,2Ko]=[hi|lo], W:[N,2Ko]=[hi|lo]. acc += Ahi*Whi + Alo*Whi + Ahi*Wlo.
// BK=64, 256 threads (8 warps, 2m x 4n, each 64x64), double-buffered cp.async.
// Smem/stage: Ahi,Alo (128x144B) + Bhi,Blo (256x144B) = 108 KB; 2 stages 216 KB.
// EPI: 1=bias 2=relu 4=+res(fp32) 8=bf16 hi/lo out (else fp32 out)
#define TILEA  18432u             // 128 * 144
#define TILEB  36864u             // 256 * 144
#define OFF_AH 0u
#define OFF_AL 18432u
#define OFF_BH 36864u
#define OFF_BL 73728u
#define STG    110592u            // per stage
#define GSMEM  221184             // 2 stages

template <int EPI>
__global__ __launch_bounds__(256, 1)
void mma_gemm(const __nv_bfloat16* __restrict__ A, const __nv_bfloat16* __restrict__ W,
              const float* __restrict__ bias, const float* __restrict__ res,
              float* __restrict__ C, __nv_bfloat16* __restrict__ Cbf, int Nn, int Ko) {
    extern __shared__ __align__(1024) char smem[];
    const uint32_t sb = smem_u32(smem);
    const int tid = threadIdx.x;
    const int wid = tid >> 5, lane = tid & 31;
    const int m0 = blockIdx.y * 128, n0 = blockIdx.x * 256;
    const int wm = wid & 1, wn = wid >> 1;
    const int nk = Ko >> 6;
    const int Kp = 2 * Ko;

    const __nv_bfloat16* srcA = A + (size_t)m0 * Kp;
    const __nv_bfloat16* srcW = W + (size_t)n0 * Kp;

    const int ldrow0 = tid >> 3;          // 0..31
    const int ldseg  = tid & 7;           // 8 segs x 8 bf16 = 64 cols
    const uint32_t ldoff0 = (uint32_t)(ldrow0 * 144 + ldseg * 16);

    // ldmatrix per-lane offsets (within a tile)
    const int lr = lane & 7, grp = lane >> 3;
    uint32_t aOff[4], bOff[4];
    #pragma unroll
    for (int mi = 0; mi < 4; mi++)
        aOff[mi] = (uint32_t)((wm * 64 + mi * 16 + lr + (grp & 1) * 8) * 144 +
                              ((grp >> 1) * 8) * 2);
    #pragma unroll
    for (int nj = 0; nj < 4; nj++)
        bOff[nj] = (uint32_t)((wn * 64 + nj * 16 + lr + (grp >> 1) * 8) * 144 +
                              ((grp & 1) * 8) * 2);

    float acc[4][8][4];
    #pragma unroll
    for (int i = 0; i < 4; i++)
        #pragma unroll
        for (int j = 0; j < 8; j++)
            #pragma unroll
            for (int e = 0; e < 4; e++) acc[i][j][e] = 0.0f;

    auto load_stage = [&](int kt, int buf) {
        uint32_t base = sb + (uint32_t)buf * STG;
        const __nv_bfloat16* ah = srcA + kt * 64;
        const __nv_bfloat16* al = ah + Ko;
        const __nv_bfloat16* wh = srcW + kt * 64;
        const __nv_bfloat16* wl = wh + Ko;
        #pragma unroll
        for (int i = 0; i < 4; i++) {
            int row = ldrow0 + i * 32;
            size_t roff = (size_t)row * Kp + ldseg * 8;
            uint32_t off = ldoff0 + (uint32_t)(i * 32 * 144);
            cpasync16(base + OFF_AH + off, ah + roff);
            cpasync16(base + OFF_AL + off, al + roff);
        }
        #pragma unroll
        for (int i = 0; i < 8; i++) {
            int row = ldrow0 + i * 32;
            size_t roff = (size_t)row * Kp + ldseg * 8;
            uint32_t off = ldoff0 + (uint32_t)(i * 32 * 144);
            cpasync16(base + OFF_BH + off, wh + roff);
            cpasync16(base + OFF_BL + off, wl + roff);
        }
        CP_COMMIT();
    };

    load_stage(0, 0);
    for (int kt = 0; kt < nk; kt++) {
        int buf = kt & 1;
        if (kt + 1 < nk) { load_stage(kt + 1, buf ^ 1); CP_WAIT1(); }
        else             { CP_WAIT0(); }
        __syncthreads();
        uint32_t base = sb + (uint32_t)buf * STG;
        #pragma unroll
        for (int ks = 0; ks < 4; ks++) {
            uint32_t ahf[4][4], alf[4][4];
            #pragma unroll
            for (int mi = 0; mi < 4; mi++) {
                LDMX4(ahf[mi], base + OFF_AH + aOff[mi] + ks * 32);
                LDMX4(alf[mi], base + OFF_AL + aOff[mi] + ks * 32);
            }
            uint32_t bhf[8][2], blf[8][2];
            #pragma unroll
            for (int nj = 0; nj < 4; nj++) {
                uint32_t th[4], tl[4];
                LDMX4(th, base + OFF_BH + bOff[nj] + ks * 32);
                LDMX4(tl, base + OFF_BL + bOff[nj] + ks * 32);
                bhf[2 * nj][0] = th[0];     bhf[2 * nj][1] = th[1];
                bhf[2 * nj + 1][0] = th[2]; bhf[2 * nj + 1][1] = th[3];
                blf[2 * nj][0] = tl[0];     blf[2 * nj][1] = tl[1];
                blf[2 * nj + 1][0] = tl[2]; blf[2 * nj + 1][1] = tl[3];
            }
            #pragma unroll
            for (int mi = 0; mi < 4; mi++)
                #pragma unroll
                for (int ni = 0; ni < 8; ni++) {
                    mma16816(acc[mi][ni][0], acc[mi][ni][1], acc[mi][ni][2], acc[mi][ni][3],
                             ahf[mi][0], ahf[mi][1], ahf[mi][2], ahf[mi][3],
                             bhf[ni][0], bhf[ni][1]);
                    mma16816(acc[mi][ni][0], acc[mi][ni][1], acc[mi][ni][2], acc[mi][ni][3],
                             alf[mi][0], alf[mi][1], alf[mi][2], alf[mi][3],
                             bhf[ni][0], bhf[ni][1]);
                    mma16816(acc[mi][ni][0], acc[mi][ni][1], acc[mi][ni][2], acc[mi][ni][3],
                             ahf[mi][0], ahf[mi][1], ahf[mi][2], ahf[mi][3],
                             blf[ni][0], blf[ni][1]);
                }
        }
        __syncthreads();
    }

    // epilogue
    const int gm = m0 + wm * 64;
    const int gn = n0 + wn * 64;
    const int rr = lane >> 2;
    const int cc = (lane & 3) * 2;
    #pragma unroll
    for (int mi = 0; mi < 4; mi++) {
        #pragma unroll
        for (int ni = 0; ni < 8; ni++) {
            int col = gn + ni * 8 + cc;
            float2 bv = make_float2(0.f, 0.f);
            if (EPI & 1) bv = *(const float2*)(bias + col);
            #pragma unroll
            for (int hh = 0; hh < 2; hh++) {
                int row = gm + mi * 16 + rr + hh * 8;
                float v0 = acc[mi][ni][2 * hh];
                float v1 = acc[mi][ni][2 * hh + 1];
                if (EPI & 1) { v0 += bv.x; v1 += bv.y; }
                if (EPI & 2) { v0 = fmaxf(v0, 0.0f); v1 = fmaxf(v1, 0.0f); }
                if (EPI & 4) {
                    float2 r2 = *(const float2*)(res + (size_t)row * Nn + col);
                    v0 += r2.x; v1 += r2.y;
                }
                if (EPI & 8) {
                    __nv_bfloat16* pr = Cbf + (size_t)row * (2 * Nn) + col;
                    __nv_bfloat162 h2, l2;
                    h2.x = __float2bfloat16(v0);
                    h2.y = __float2bfloat16(v1);
                    l2.x = __float2bfloat16(v0 - __bfloat162float(h2.x));
                    l2.y = __float2bfloat16(v1 - __bfloat162float(h2.y));
                    *(__nv_bfloat162*)(pr)      = h2;
                    *(__nv_bfloat162*)(pr + Nn) = l2;
                } else {
                    *(float2*)(C + (size_t)row * Nn + col) = make_float2(v0, v1);
                }
            }
        }
    }
}

// ---------------- launch ----------------
extern "C" void kernel_launch(void* const* d_in, const int* in_sizes, int n_in,
                              void* d_out, int out_size) {
    const float* x    = (const float*)d_in[0];
    const float* Wq   = (const float*)d_in[1];
    const float* Wk   = (const float*)d_in[2];
    const float* Wv   = (const float*)d_in[3];
    const float* lq1  = (const float*)d_in[4];
    const float* lq2  = (const float*)d_in[5];
    const float* lk1  = (const float*)d_in[6];
    const float* lk2  = (const float*)d_in[7];
    const float* Wo   = (const float*)d_in[8];
    const float* bo   = (const float*)d_in[9];
    const float* ln1g = (const float*)d_in[10];
    const float* ln1b = (const float*)d_in[11];
    const float* ln2g = (const float*)d_in[12];
    const float* ln2b = (const float*)d_in[13];
    const float* W1   = (const float*)d_in[14];
    const float* b1   = (const float*)d_in[15];
    const float* W2   = (const float*)d_in[16];
    const float* b2   = (const float*)d_in[17];
    float* out = (float*)d_out;

    __nv_bfloat16 *phbf, *pattnbf, *ph2bf, *pffnbf, *pwqkv, *pwo, *pw1, *pw2;
    float *pqkv, *pconn;
    cudaGetSymbolAddress((void**)&phbf,    g_hbf);
    cudaGetSymbolAddress((void**)&pqkv,    g_qkv);
    cudaGetSymbolAddress((void**)&pattnbf, g_attnbf);
    cudaGetSymbolAddress((void**)&pconn,   g_conn);
    cudaGetSymbolAddress((void**)&ph2bf,   g_h2bf);
    cudaGetSymbolAddress((void**)&pffnbf,  g_ffnbf);
    cudaGetSymbolAddress((void**)&pwqkv,   g_wqkv);
    cudaGetSymbolAddress((void**)&pwo,     g_wo);
    cudaGetSymbolAddress((void**)&pw1,     g_w1);
    cudaGetSymbolAddress((void**)&pw2,     g_w2);

    cudaFuncSetAttribute(mma_gemm<0>,  cudaFuncAttributeMaxDynamicSharedMemorySize, GSMEM);
    cudaFuncSetAttribute(mma_gemm<5>,  cudaFuncAttributeMaxDynamicSharedMemorySize, GSMEM);
    cudaFuncSetAttribute(mma_gemm<11>, cudaFuncAttributeMaxDynamicSharedMemorySize, GSMEM);

    lambda_kernel<<<1, 32>>>(lq1, lq2, lk1, lk2);

    // weight converts (fp32 -> bf16 hi|lo); Q,K,V stacked into one [3072, 2048]
    int tw = DMODEL * DMODEL;
    convert_w_kernel<<<tw / 256, 256>>>(Wq, pwqkv,                                   tw, 10);
    convert_w_kernel<<<tw / 256, 256>>>(Wk, pwqkv + (size_t)DMODEL * 2 * DMODEL,     tw, 10);
    convert_w_kernel<<<tw / 256, 256>>>(Wv, pwqkv + (size_t)2 * DMODEL * 2 * DMODEL, tw, 10);
    convert_w_kernel<<<tw / 256, 256>>>(Wo, pwo, tw, 10);
    int t1 = FFDIM * DMODEL;
    convert_w_kernel<<<t1 / 256, 256>>>(W1, pw1, t1, 10);
    convert_w_kernel<<<t1 / 256, 256>>>(W2, pw2, t1, 12);

    // LN1: x -> hbf
    ln_kernel<<<Mrows, 256>>>(x, ln1g, ln1b, phbf);

    // fused QKV: [M,1024] x [3072,1024]^T -> [M,3072]
    dim3 gqkv(QKVN / 256, Mrows / 128);   // (12,128)
    mma_gemm<0><<<gqkv, 256, GSMEM>>>(phbf, pwqkv, nullptr, nullptr, pqkv, nullptr, QKVN, DMODEL);

    attn_kernel<<<Mrows / 2, 64>>>(pqkv, pattnbf);

    // conn = x + attn @ Wo^T + bo
    dim3 gq(DMODEL / 256, Mrows / 128);   // (4,128)
    mma_gemm<5><<<gq, 256, GSMEM>>>(pattnbf, pwo, bo, x, pconn, nullptr, DMODEL, DMODEL);

    // LN2: conn -> h2bf
    ln_kernel<<<Mrows, 256>>>(pconn, ln2g, ln2b, ph2bf);

    // ffn = relu(h2 @ W1^T + b1) -> bf16 hi|lo
    dim3 g1(FFDIM / 256, Mrows / 128);    // (16,128)
    mma_gemm<11><<<g1, 256, GSMEM>>>(ph2bf, pw1, b1, nullptr, nullptr, pffnbf, FFDIM, DMODEL);

    // out = conn + ffn @ W2^T + b2
    mma_gemm<5><<<gq, 256, GSMEM>>>(pffnbf, pw2, b2, pconn, out, nullptr, DMODEL, FFDIM);
}